// round 1
// baseline (speedup 1.0000x reference)
#include <cuda_runtime.h>
#include <math.h>

#define B_   2
#define T_   2048
#define H_   16
#define DH   64
#define DL   32
#define CDIM 1024

#define Y_ELEMS  ((size_t)B_*T_*CDIM)          // 4194304
#define KL_ELEMS ((size_t)B_*T_*H_*DL)         // 2097152

// ---- scratch (device globals; no allocation allowed) ----
__device__ float g_q[(size_t)B_*T_*H_*DH];
__device__ float g_k[(size_t)B_*T_*H_*DH];
__device__ float g_v[(size_t)B_*T_*H_*DH];
__device__ float g_y[(size_t)B_*T_*H_*DH];
__device__ float g_cos[T_*DH];
__device__ float g_sin[T_*DH];

// ============================================================
// RoPE table: cos/sin of fp32 angle, evaluated in fp64
// reference: inv_freq[j] = 10000^(-j/32); angle = t * inv_freq (fp32)
// ============================================================
__global__ void rope_table_kernel() {
    int t = blockIdx.x;
    int c = threadIdx.x;        // 0..63
    int j = c & 31;
    double inv = pow(10000.0, -(double)j / 32.0);
    float  ang = (float)t * (float)inv;   // fp32 multiply, like reference
    double s, cc;
    sincos((double)ang, &s, &cc);
    g_cos[t * DH + c] = (float)cc;
    g_sin[t * DH + c] = (float)s;
}

// ============================================================
// SGEMM: C[M,N] = A[M,K] @ W[N,K]^T   (both K-contiguous)
// 128x128x16 tile, 256 threads, 8x8 per thread (split 4+4)
// M,N,K all multiples of tile sizes for every call here.
// ============================================================
__device__ __forceinline__ void sgemm_body(
    const float* __restrict__ A, const float* __restrict__ W,
    float* __restrict__ C, int K, int N)
{
    __shared__ float As[16][128];
    __shared__ float Ws[16][128];
    const int tid = threadIdx.x;
    const int bm  = blockIdx.y << 7;
    const int bn  = blockIdx.x << 7;
    const int tx  = tid & 15, ty = tid >> 4;
    const int lr  = tid >> 2;
    const int lc  = (tid & 3) << 2;

    float acc[8][8];
#pragma unroll
    for (int i = 0; i < 8; i++)
#pragma unroll
        for (int j = 0; j < 8; j++) acc[i][j] = 0.f;

    const float* Arow0 = A + (size_t)(bm + lr) * K + lc;
    const float* Arow1 = Arow0 + (size_t)64 * K;
    const float* Wrow0 = W + (size_t)(bn + lr) * K + lc;
    const float* Wrow1 = Wrow0 + (size_t)64 * K;

    for (int k0 = 0; k0 < K; k0 += 16) {
        float4 a0 = *(const float4*)(Arow0 + k0);
        float4 a1 = *(const float4*)(Arow1 + k0);
        float4 w0 = *(const float4*)(Wrow0 + k0);
        float4 w1 = *(const float4*)(Wrow1 + k0);
        __syncthreads();
        As[lc+0][lr]    = a0.x; As[lc+1][lr]    = a0.y; As[lc+2][lr]    = a0.z; As[lc+3][lr]    = a0.w;
        As[lc+0][lr+64] = a1.x; As[lc+1][lr+64] = a1.y; As[lc+2][lr+64] = a1.z; As[lc+3][lr+64] = a1.w;
        Ws[lc+0][lr]    = w0.x; Ws[lc+1][lr]    = w0.y; Ws[lc+2][lr]    = w0.z; Ws[lc+3][lr]    = w0.w;
        Ws[lc+0][lr+64] = w1.x; Ws[lc+1][lr+64] = w1.y; Ws[lc+2][lr+64] = w1.z; Ws[lc+3][lr+64] = w1.w;
        __syncthreads();
#pragma unroll
        for (int kk = 0; kk < 16; kk++) {
            float4 aA = *(const float4*)&As[kk][ty << 2];
            float4 aB = *(const float4*)&As[kk][64 + (ty << 2)];
            float4 bA = *(const float4*)&Ws[kk][tx << 2];
            float4 bB = *(const float4*)&Ws[kk][64 + (tx << 2)];
            float ar[8] = {aA.x, aA.y, aA.z, aA.w, aB.x, aB.y, aB.z, aB.w};
            float br[8] = {bA.x, bA.y, bA.z, bA.w, bB.x, bB.y, bB.z, bB.w};
#pragma unroll
            for (int i = 0; i < 8; i++)
#pragma unroll
                for (int j = 0; j < 8; j++)
                    acc[i][j] = fmaf(ar[i], br[j], acc[i][j]);
        }
    }
#pragma unroll
    for (int i = 0; i < 8; i++) {
        int r = (i < 4) ? ((ty << 2) + i) : (64 + (ty << 2) + i - 4);
        float4 o0 = make_float4(acc[i][0], acc[i][1], acc[i][2], acc[i][3]);
        float4 o1 = make_float4(acc[i][4], acc[i][5], acc[i][6], acc[i][7]);
        *(float4*)&C[(size_t)(bm + r) * N + bn + (tx << 2)]      = o0;
        *(float4*)&C[(size_t)(bm + r) * N + bn + 64 + (tx << 2)] = o1;
    }
}

__global__ void __launch_bounds__(256, 2)
sgemm_nt(const float* __restrict__ A, const float* __restrict__ W,
         float* __restrict__ C, int K, int N)
{
    sgemm_body(A, W, C, K, N);
}

// k_lat and v_lat share a launch: blockIdx.z selects the pair.
__global__ void __launch_bounds__(256, 2)
sgemm_kv(const float* __restrict__ A,
         const float* __restrict__ Wk, const float* __restrict__ Wv,
         float* __restrict__ Ck, float* __restrict__ Cv, int K, int N)
{
    sgemm_body(A, blockIdx.z ? Wv : Wk, blockIdx.z ? Cv : Ck, K, N);
}

// ============================================================
// Latent up-projection (Dl=32 -> Dh=64) + RoPE on k and q, v copy.
// One block per (b,t), 256 threads; each thread does 2 (head, pair) items.
// ============================================================
__global__ void __launch_bounds__(256)
upproj_rope_kernel(const float* __restrict__ klat, const float* __restrict__ vlat,
                   const float* __restrict__ Wku,  const float* __restrict__ Wvu)
{
    const int bt = blockIdx.x;           // b*T + t
    const int t  = bt & (T_ - 1);
    __shared__ float skl[512], svl[512];
    __shared__ float swk[64 * 33], swv[64 * 33];   // padded stride 33
    const int tid = threadIdx.x;

    skl[tid]       = klat[(size_t)bt * 512 + tid];
    skl[tid + 256] = klat[(size_t)bt * 512 + tid + 256];
    svl[tid]       = vlat[(size_t)bt * 512 + tid];
    svl[tid + 256] = vlat[(size_t)bt * 512 + tid + 256];
    for (int i = tid; i < 64 * 32; i += 256) {
        int d = i >> 5, l = i & 31;
        swk[d * 33 + l] = Wku[i];
        swv[d * 33 + l] = Wvu[i];
    }
    __syncthreads();

#pragma unroll
    for (int p = tid; p < 512; p += 256) {
        const int h  = p >> 5, i = p & 31;
        const int d0 = i << 1, d1 = d0 + 1;
        const float* kl  = &skl[h << 5];
        const float* vl  = &svl[h << 5];
        const float* wk0 = &swk[d0 * 33];
        const float* wk1 = &swk[d1 * 33];
        const float* wv0 = &swv[d0 * 33];
        const float* wv1 = &swv[d1 * 33];
        float k0 = 0.f, k1 = 0.f, v0 = 0.f, v1 = 0.f;
#pragma unroll
        for (int l = 0; l < 32; l++) {
            float klv = kl[l], vlv = vl[l];
            k0 = fmaf(klv, wk0[l], k0);
            k1 = fmaf(klv, wk1[l], k1);
            v0 = fmaf(vlv, wv0[l], v0);
            v1 = fmaf(vlv, wv1[l], v1);
        }
        const float c0 = g_cos[t * DH + d0], s0 = g_sin[t * DH + d0];
        const float c1 = g_cos[t * DH + d1], s1 = g_sin[t * DH + d1];
        const size_t gi = ((size_t)bt * H_ + h) * DH;
        // rope(k):  out[2i] = k0*c0 - k1*s0 ; out[2i+1] = k1*c1 + k0*s1
        g_k[gi + d0] = k0 * c0 - k1 * s0;
        g_k[gi + d1] = k1 * c1 + k0 * s1;
        g_v[gi + d0] = v0;
        g_v[gi + d1] = v1;
        // rope(q) in place
        float q0v = g_q[gi + d0], q1v = g_q[gi + d1];
        g_q[gi + d0] = q0v * c0 - q1v * s0;
        g_q[gi + d1] = q1v * c1 + q0v * s1;
    }
}

// ============================================================
// Causal flash attention, fp32. 64x64 tiles, 256 threads,
// thread (tx,ty) owns rows {ty+16i}, cols {tx+16j}.
// Layouts: q,k,v,y all (B,T,H,Dh) row-major.
// ============================================================
#define ATT_SMEM (4 * 64 * 65 * 4)

__global__ void __launch_bounds__(256)
attn_kernel()
{
    extern __shared__ float sm[];
    float* Qs = sm;                 // 64 x 65
    float* Ks = sm + 64 * 65;
    float* Vs = sm + 2 * 64 * 65;
    float* Ps = sm + 3 * 64 * 65;
    const int tid = threadIdx.x;
    const int tx = tid & 15, ty = tid >> 4;
    const int qt = blockIdx.x, h = blockIdx.y, b = blockIdx.z;
    const int q0 = qt << 6;

    // load Q tile, pre-scaled by 1/sqrt(Dh)
    for (int i = tid; i < 64 * 16; i += 256) {
        int r = i >> 4, c4 = (i & 15) << 2;
        float4 v = *(const float4*)&g_q[((((size_t)b * T_ + q0 + r) * H_ + h) << 6) + c4];
        float* dst = &Qs[r * 65 + c4];
        dst[0] = v.x * 0.125f; dst[1] = v.y * 0.125f;
        dst[2] = v.z * 0.125f; dst[3] = v.w * 0.125f;
    }

    float m[4], l[4], acc[4][4];
#pragma unroll
    for (int i = 0; i < 4; i++) {
        m[i] = -1e30f; l[i] = 0.f;
#pragma unroll
        for (int j = 0; j < 4; j++) acc[i][j] = 0.f;
    }

    for (int kt = 0; kt <= qt; kt++) {
        const int k0 = kt << 6;
        __syncthreads();   // protects Ks/Vs/Ps from previous iteration readers
        for (int i = tid; i < 64 * 16; i += 256) {
            int r = i >> 4, c4 = (i & 15) << 2;
            size_t g = ((((size_t)b * T_ + k0 + r) * H_ + h) << 6) + c4;
            float4 kv = *(const float4*)&g_k[g];
            float4 vv = *(const float4*)&g_v[g];
            float* kd = &Ks[r * 65 + c4];
            kd[0] = kv.x; kd[1] = kv.y; kd[2] = kv.z; kd[3] = kv.w;
            float* vd = &Vs[r * 65 + c4];
            vd[0] = vv.x; vd[1] = vv.y; vd[2] = vv.z; vd[3] = vv.w;
        }
        __syncthreads();

        // S = Q K^T
        float s[4][4];
#pragma unroll
        for (int i = 0; i < 4; i++)
#pragma unroll
            for (int j = 0; j < 4; j++) s[i][j] = 0.f;
#pragma unroll 8
        for (int d = 0; d < 64; d++) {
            float a[4], bb[4];
#pragma unroll
            for (int i = 0; i < 4; i++) a[i]  = Qs[(ty + (i << 4)) * 65 + d];
#pragma unroll
            for (int j = 0; j < 4; j++) bb[j] = Ks[(tx + (j << 4)) * 65 + d];
#pragma unroll
            for (int i = 0; i < 4; i++)
#pragma unroll
                for (int j = 0; j < 4; j++)
                    s[i][j] = fmaf(a[i], bb[j], s[i][j]);
        }

        // causal mask: only the diagonal tile needs it
        if (kt == qt) {
#pragma unroll
            for (int i = 0; i < 4; i++)
#pragma unroll
                for (int j = 0; j < 4; j++)
                    if ((tx + (j << 4)) > (ty + (i << 4))) s[i][j] = -1e30f;
        }

        // online softmax update
#pragma unroll
        for (int i = 0; i < 4; i++) {
            float mt = fmaxf(fmaxf(s[i][0], s[i][1]), fmaxf(s[i][2], s[i][3]));
#pragma unroll
            for (int o = 8; o >= 1; o >>= 1)
                mt = fmaxf(mt, __shfl_xor_sync(0xffffffffu, mt, o));
            float mn = fmaxf(m[i], mt);
            float al = __expf(m[i] - mn);
            m[i] = mn;
            float rs = 0.f;
#pragma unroll
            for (int j = 0; j < 4; j++) {
                float p = __expf(s[i][j] - mn);
                rs += p;
                Ps[(ty + (i << 4)) * 65 + tx + (j << 4)] = p;
            }
#pragma unroll
            for (int o = 8; o >= 1; o >>= 1)
                rs += __shfl_xor_sync(0xffffffffu, rs, o);
            l[i] = l[i] * al + rs;
#pragma unroll
            for (int j = 0; j < 4; j++) acc[i][j] *= al;
        }
        __syncthreads();

        // O += P V
#pragma unroll 4
        for (int jj = 0; jj < 64; jj++) {
            float pv[4], vv[4];
#pragma unroll
            for (int i = 0; i < 4; i++) pv[i] = Ps[(ty + (i << 4)) * 65 + jj];
#pragma unroll
            for (int j = 0; j < 4; j++) vv[j] = Vs[jj * 65 + tx + (j << 4)];
#pragma unroll
            for (int i = 0; i < 4; i++)
#pragma unroll
                for (int j = 0; j < 4; j++)
                    acc[i][j] = fmaf(pv[i], vv[j], acc[i][j]);
        }
    }

    // write y (B,T,H,Dh)
#pragma unroll
    for (int i = 0; i < 4; i++) {
        float inv = 1.f / l[i];
#pragma unroll
        for (int j = 0; j < 4; j++) {
            int r = ty + (i << 4), c = tx + (j << 4);
            g_y[((((size_t)b * T_ + q0 + r) * H_ + h) << 6) + c] = acc[i][j] * inv;
        }
    }
}

// ============================================================
// launch
// ============================================================
extern "C" void kernel_launch(void* const* d_in, const int* in_sizes, int n_in,
                              void* d_out, int out_size)
{
    const float* x   = (const float*)d_in[0];
    const float* Wq  = (const float*)d_in[1];
    const float* Wk  = (const float*)d_in[2];
    const float* Wv  = (const float*)d_in[3];
    const float* Wku = (const float*)d_in[4];
    const float* Wvu = (const float*)d_in[5];
    const float* Wc  = (const float*)d_in[6];

    float* out      = (float*)d_out;
    float* y_out    = out;                         // (B,T,1024)
    float* klat_out = out + Y_ELEMS;               // (B,T,H,Dl)
    float* vlat_out = out + Y_ELEMS + KL_ELEMS;    // (B,T,H,Dl)

    float *qp, *yp;
    cudaGetSymbolAddress((void**)&qp, g_q);
    cudaGetSymbolAddress((void**)&yp, g_y);
    cudaFuncSetAttribute(attn_kernel, cudaFuncAttributeMaxDynamicSharedMemorySize, ATT_SMEM);

    // 1. rope tables (input-independent, deterministic)
    rope_table_kernel<<<T_, 64>>>();

    // 2. q = x @ Wq^T  -> g_q  (4096 x 1024 x 1024)
    dim3 gq(CDIM / 128, (B_ * T_) / 128);
    sgemm_nt<<<gq, 256>>>(x, Wq, qp, CDIM, CDIM);

    // 3. k_lat / v_lat -> d_out regions (4096 x 512 x 1024), fused launch
    dim3 gkv(512 / 128, (B_ * T_) / 128, 2);
    sgemm_kv<<<gkv, 256>>>(x, Wk, Wv, klat_out, vlat_out, CDIM, 512);

    // 4. up-project + RoPE (k,q), v
    upproj_rope_kernel<<<B_ * T_, 256>>>(klat_out, vlat_out, Wku, Wvu);

    // 5. causal flash attention -> g_y
    dim3 ga(T_ / 64, H_, B_);
    attn_kernel<<<ga, 256, ATT_SMEM>>>();

    // 6. y = attn @ Wc^T -> d_out
    sgemm_nt<<<gq, 256>>>(yp, Wc, y_out, CDIM, CDIM);
}

// round 3
// speedup vs baseline: 1.3196x; 1.3196x over previous
#include <cuda_runtime.h>
#include <cuda_bf16.h>
#include <math.h>
#include <stdint.h>

#define B_   2
#define T_   2048
#define H_   16
#define DH   64
#define DL   32
#define CDIM 1024

#define Y_ELEMS  ((size_t)B_*T_*CDIM)          // 4194304
#define KL_ELEMS ((size_t)B_*T_*H_*DL)         // 2097152

// ---- scratch (device globals; no allocation allowed) ----
__device__ float g_q[(size_t)B_*T_*H_*DH];
__device__ float g_k[(size_t)B_*T_*H_*DH];
__device__ float g_v[(size_t)B_*T_*H_*DH];
__device__ float g_y[(size_t)B_*T_*H_*DH];
__device__ float g_cos[T_*DH];
__device__ float g_sin[T_*DH];

// bf16 split-precision copies
__device__ __nv_bfloat16 g_xh[(size_t)B_*T_*CDIM];
__device__ __nv_bfloat16 g_xl[(size_t)B_*T_*CDIM];
__device__ __nv_bfloat16 g_yh[(size_t)B_*T_*CDIM];
__device__ __nv_bfloat16 g_yl[(size_t)B_*T_*CDIM];
// weights packed: Wq @0 (1M), Wk @1M (0.5M), Wv @1.5M (0.5M), Wc @2M (1M)
__device__ __nv_bfloat16 g_wh[3u*1024*1024];
__device__ __nv_bfloat16 g_wl[3u*1024*1024];
#define WQ_OFF 0u
#define WK_OFF (1024u*1024u)
#define WV_OFF (1536u*1024u)
#define WC_OFF (2048u*1024u)

// ============================================================
// PTX helpers (mma.sync / ldmatrix / cp.async)
// ============================================================
__device__ __forceinline__ uint32_t smem_u32(const void* p) {
    uint32_t a;
    asm("{ .reg .u64 t; cvta.to.shared.u64 t, %1; cvt.u32.u64 %0, t; }"
        : "=r"(a) : "l"(p));
    return a;
}

__device__ __forceinline__ void cp16(uint32_t dst, const void* src) {
    asm volatile("cp.async.cg.shared.global [%0], [%1], 16;\n"
                 :: "r"(dst), "l"(src));
}
__device__ __forceinline__ void cp_commit() {
    asm volatile("cp.async.commit_group;\n" ::: "memory");
}
template<int N> __device__ __forceinline__ void cp_wait() {
    asm volatile("cp.async.wait_group %0;\n" :: "n"(N) : "memory");
}

__device__ __forceinline__ void ldm_x4(uint32_t* r, uint32_t addr) {
    asm volatile("ldmatrix.sync.aligned.m8n8.x4.shared.b16 {%0,%1,%2,%3}, [%4];"
        : "=r"(r[0]), "=r"(r[1]), "=r"(r[2]), "=r"(r[3]) : "r"(addr));
}

__device__ __forceinline__ void mma_bf16(float* c, const uint32_t* a, const uint32_t* b) {
    asm volatile("mma.sync.aligned.m16n8k16.row.col.f32.bf16.bf16.f32 "
        "{%0,%1,%2,%3}, {%4,%5,%6,%7}, {%8,%9}, {%0,%1,%2,%3};\n"
        : "+f"(c[0]), "+f"(c[1]), "+f"(c[2]), "+f"(c[3])
        : "r"(a[0]), "r"(a[1]), "r"(a[2]), "r"(a[3]), "r"(b[0]), "r"(b[1]));
}

// ============================================================
// fp32 -> (bf16 hi, bf16 lo) split
// ============================================================
__global__ void __launch_bounds__(256)
split_bf16_kernel(const float* __restrict__ in,
                  __nv_bfloat16* __restrict__ hi,
                  __nv_bfloat16* __restrict__ lo, int n4)
{
    int i = blockIdx.x * blockDim.x + threadIdx.x;
    if (i >= n4) return;
    float4 v = ((const float4*)in)[i];
    __nv_bfloat16 h0 = __float2bfloat16(v.x);
    __nv_bfloat16 h1 = __float2bfloat16(v.y);
    __nv_bfloat16 h2 = __float2bfloat16(v.z);
    __nv_bfloat16 h3 = __float2bfloat16(v.w);
    __nv_bfloat16 l0 = __float2bfloat16(v.x - __bfloat162float(h0));
    __nv_bfloat16 l1 = __float2bfloat16(v.y - __bfloat162float(h1));
    __nv_bfloat16 l2 = __float2bfloat16(v.z - __bfloat162float(h2));
    __nv_bfloat16 l3 = __float2bfloat16(v.w - __bfloat162float(h3));
    ((__nv_bfloat162*)hi)[2*i]   = __nv_bfloat162(h0, h1);
    ((__nv_bfloat162*)hi)[2*i+1] = __nv_bfloat162(h2, h3);
    ((__nv_bfloat162*)lo)[2*i]   = __nv_bfloat162(l0, l1);
    ((__nv_bfloat162*)lo)[2*i+1] = __nv_bfloat162(l2, l3);
}

// ============================================================
// HMMA GEMM, bf16 split-precision (3 MMA), C = A @ W^T (fp32 out)
// A: [M,K] hi/lo bf16 (K-contig). W: [N,K] hi/lo bf16 (K-contig)
//   -> exactly mma.row.col's col-major B; ldmatrix non-trans.
// CTA 128x128, 256 threads (8 warps, 2x4), warp tile 64x32.
// K-chunk 32 bf16, double-buffered cp.async.
// smem rows padded to 40 bf16 (80B) -> conflict-free ldmatrix.
// ============================================================
#define GS_ROWB   80                    // bytes per smem row
#define GS_MAT    (128 * GS_ROWB)       // 10240 B per matrix
#define GS_STAGE  (4 * GS_MAT)          // Ah, Al, Bh, Bl
#define GS_SMEM   (2 * GS_STAGE)        // 81920 B

__device__ __forceinline__ void hgemm_load_chunk(
    const __nv_bfloat16* __restrict__ Ah, const __nv_bfloat16* __restrict__ Al,
    const __nv_bfloat16* __restrict__ Bh, const __nv_bfloat16* __restrict__ Bl,
    int K, int bm, int bn, int k0, uint32_t sbase, int tid)
{
#pragma unroll
    for (int i = 0; i < 8; i++) {
        int task = tid + (i << 8);      // 0..2047
        int op   = task >> 9;           // 0:Ah 1:Al 2:Bh 3:Bl
        int t2   = task & 511;
        int row  = t2 >> 2;             // 0..127
        int g    = t2 & 3;              // 16B granule (8 bf16)
        const __nv_bfloat16* base;
        int grow;
        if      (op == 0) { base = Ah; grow = bm + row; }
        else if (op == 1) { base = Al; grow = bm + row; }
        else if (op == 2) { base = Bh; grow = bn + row; }
        else              { base = Bl; grow = bn + row; }
        const void* src = base + (size_t)grow * K + k0 + (g << 3);
        uint32_t dst = sbase + op * GS_MAT + row * GS_ROWB + (g << 4);
        cp16(dst, src);
    }
}

__device__ __forceinline__ void hgemm_body(
    const __nv_bfloat16* __restrict__ Ah, const __nv_bfloat16* __restrict__ Al,
    const __nv_bfloat16* __restrict__ Bh, const __nv_bfloat16* __restrict__ Bl,
    float* __restrict__ C, int K, int N)
{
    extern __shared__ __align__(128) char sm[];
    const uint32_t smb = smem_u32(sm);
    const int tid  = threadIdx.x;
    const int wid  = tid >> 5;
    const int lane = tid & 31;
    const int bm = blockIdx.y << 7;
    const int bn = blockIdx.x << 7;
    const int wm = (wid >> 2) << 6;     // warp M offset (0/64)
    const int wn = (wid & 3) << 5;      // warp N offset (0/32/64/96)

    // ldmatrix lane coordinates
    const int rA = (lane & 7) + ((lane >> 3) & 1) * 8;
    const int cA = (lane >> 4) << 3;
    const int rB = (lane & 7) + ((lane >> 4) << 3);
    const int cB = ((lane >> 3) & 1) << 3;

    float acc[4][4][4];
#pragma unroll
    for (int mt = 0; mt < 4; mt++)
#pragma unroll
        for (int nt = 0; nt < 4; nt++)
#pragma unroll
            for (int e = 0; e < 4; e++) acc[mt][nt][e] = 0.f;

    const int NC = K >> 5;              // chunks of 32

    hgemm_load_chunk(Ah, Al, Bh, Bl, K, bm, bn, 0, smb, tid);
    cp_commit();
    hgemm_load_chunk(Ah, Al, Bh, Bl, K, bm, bn, 32, smb + GS_STAGE, tid);
    cp_commit();

    for (int c = 0; c < NC; c++) {
        const uint32_t sb = smb + (c & 1) * GS_STAGE;
        if (c + 1 < NC) cp_wait<1>(); else cp_wait<0>();
        __syncthreads();

#pragma unroll
        for (int ks = 0; ks < 2; ks++) {
            const int k0 = ks << 4;
            uint32_t ah[4][4], al[4][4], bh[2][4], bl[2][4];
#pragma unroll
            for (int mt = 0; mt < 4; mt++) {
                uint32_t ro = (uint32_t)(wm + (mt << 4) + rA) * GS_ROWB + ((k0 + cA) << 1);
                ldm_x4(ah[mt], sb + 0 * GS_MAT + ro);
                ldm_x4(al[mt], sb + 1 * GS_MAT + ro);
            }
#pragma unroll
            for (int nt2 = 0; nt2 < 2; nt2++) {
                uint32_t ro = (uint32_t)(wn + (nt2 << 4) + rB) * GS_ROWB + ((k0 + cB) << 1);
                ldm_x4(bh[nt2], sb + 2 * GS_MAT + ro);
                ldm_x4(bl[nt2], sb + 3 * GS_MAT + ro);
            }
#pragma unroll
            for (int mt = 0; mt < 4; mt++)
#pragma unroll
                for (int nt = 0; nt < 4; nt++) {
                    const uint32_t* bhp = &bh[nt >> 1][(nt & 1) << 1];
                    const uint32_t* blp = &bl[nt >> 1][(nt & 1) << 1];
                    mma_bf16(acc[mt][nt], ah[mt], bhp);
                    mma_bf16(acc[mt][nt], ah[mt], blp);
                    mma_bf16(acc[mt][nt], al[mt], bhp);
                }
        }
        __syncthreads();
        if (c + 2 < NC) {
            hgemm_load_chunk(Ah, Al, Bh, Bl, K, bm, bn, (c + 2) << 5,
                             smb + (c & 1) * GS_STAGE, tid);
        }
        cp_commit();
    }

    // epilogue: float2 direct stores
    const int g  = lane >> 2;
    const int tg = lane & 3;
#pragma unroll
    for (int mt = 0; mt < 4; mt++) {
        const int row0 = bm + wm + (mt << 4) + g;
#pragma unroll
        for (int nt = 0; nt < 4; nt++) {
            const int col = bn + wn + (nt << 3) + (tg << 1);
            *(float2*)&C[(size_t)row0 * N + col] =
                make_float2(acc[mt][nt][0], acc[mt][nt][1]);
            *(float2*)&C[(size_t)(row0 + 8) * N + col] =
                make_float2(acc[mt][nt][2], acc[mt][nt][3]);
        }
    }
}

__global__ void __launch_bounds__(256, 1)
hgemm_nt(const __nv_bfloat16* __restrict__ Ah, const __nv_bfloat16* __restrict__ Al,
         const __nv_bfloat16* __restrict__ Bh, const __nv_bfloat16* __restrict__ Bl,
         float* __restrict__ C, int K, int N)
{
    hgemm_body(Ah, Al, Bh, Bl, C, K, N);
}

// fused k_lat/v_lat (blockIdx.z selects)
__global__ void __launch_bounds__(256, 1)
hgemm_kv(const __nv_bfloat16* __restrict__ Ah, const __nv_bfloat16* __restrict__ Al,
         const __nv_bfloat16* __restrict__ Bkh, const __nv_bfloat16* __restrict__ Bkl,
         const __nv_bfloat16* __restrict__ Bvh, const __nv_bfloat16* __restrict__ Bvl,
         float* __restrict__ Ck, float* __restrict__ Cv, int K, int N)
{
    if (blockIdx.z) hgemm_body(Ah, Al, Bvh, Bvl, Cv, K, N);
    else            hgemm_body(Ah, Al, Bkh, Bkl, Ck, K, N);
}

// ============================================================
// RoPE table: cos/sin of fp32 angle, evaluated in fp64
// ============================================================
__global__ void rope_table_kernel() {
    int t = blockIdx.x;
    int c = threadIdx.x;        // 0..63
    int j = c & 31;
    double inv = pow(10000.0, -(double)j / 32.0);
    float  ang = (float)t * (float)inv;
    double s, cc;
    sincos((double)ang, &s, &cc);
    g_cos[t * DH + c] = (float)cc;
    g_sin[t * DH + c] = (float)s;
}

// ============================================================
// Latent up-projection (Dl=32 -> Dh=64) + RoPE on k and q, v copy.
// ============================================================
__global__ void __launch_bounds__(256)
upproj_rope_kernel(const float* __restrict__ klat, const float* __restrict__ vlat,
                   const float* __restrict__ Wku,  const float* __restrict__ Wvu)
{
    const int bt = blockIdx.x;
    const int t  = bt & (T_ - 1);
    __shared__ float skl[512], svl[512];
    __shared__ float swk[64 * 33], swv[64 * 33];
    const int tid = threadIdx.x;

    skl[tid]       = klat[(size_t)bt * 512 + tid];
    skl[tid + 256] = klat[(size_t)bt * 512 + tid + 256];
    svl[tid]       = vlat[(size_t)bt * 512 + tid];
    svl[tid + 256] = vlat[(size_t)bt * 512 + tid + 256];
    for (int i = tid; i < 64 * 32; i += 256) {
        int d = i >> 5, l = i & 31;
        swk[d * 33 + l] = Wku[i];
        swv[d * 33 + l] = Wvu[i];
    }
    __syncthreads();

#pragma unroll
    for (int p = tid; p < 512; p += 256) {
        const int h  = p >> 5, i = p & 31;
        const int d0 = i << 1, d1 = d0 + 1;
        const float* kl  = &skl[h << 5];
        const float* vl  = &svl[h << 5];
        const float* wk0 = &swk[d0 * 33];
        const float* wk1 = &swk[d1 * 33];
        const float* wv0 = &swv[d0 * 33];
        const float* wv1 = &swv[d1 * 33];
        float k0 = 0.f, k1 = 0.f, v0 = 0.f, v1 = 0.f;
#pragma unroll
        for (int l = 0; l < 32; l++) {
            float klv = kl[l], vlv = vl[l];
            k0 = fmaf(klv, wk0[l], k0);
            k1 = fmaf(klv, wk1[l], k1);
            v0 = fmaf(vlv, wv0[l], v0);
            v1 = fmaf(vlv, wv1[l], v1);
        }
        const float c0 = g_cos[t * DH + d0], s0 = g_sin[t * DH + d0];
        const float c1 = g_cos[t * DH + d1], s1 = g_sin[t * DH + d1];
        const size_t gi = ((size_t)bt * H_ + h) * DH;
        g_k[gi + d0] = k0 * c0 - k1 * s0;
        g_k[gi + d1] = k1 * c1 + k0 * s1;
        g_v[gi + d0] = v0;
        g_v[gi + d1] = v1;
        float q0v = g_q[gi + d0], q1v = g_q[gi + d1];
        g_q[gi + d0] = q0v * c0 - q1v * s0;
        g_q[gi + d1] = q1v * c1 + q0v * s1;
    }
}

// ============================================================
// Causal flash attention, fp32 (unchanged, known-correct)
// ============================================================
#define ATT_SMEM (4 * 64 * 65 * 4)

__global__ void __launch_bounds__(256)
attn_kernel()
{
    extern __shared__ float smf[];
    float* Qs = smf;
    float* Ks = smf + 64 * 65;
    float* Vs = smf + 2 * 64 * 65;
    float* Ps = smf + 3 * 64 * 65;
    const int tid = threadIdx.x;
    const int tx = tid & 15, ty = tid >> 4;
    const int qt = blockIdx.x, h = blockIdx.y, b = blockIdx.z;
    const int q0 = qt << 6;

    for (int i = tid; i < 64 * 16; i += 256) {
        int r = i >> 4, c4 = (i & 15) << 2;
        float4 v = *(const float4*)&g_q[((((size_t)b * T_ + q0 + r) * H_ + h) << 6) + c4];
        float* dst = &Qs[r * 65 + c4];
        dst[0] = v.x * 0.125f; dst[1] = v.y * 0.125f;
        dst[2] = v.z * 0.125f; dst[3] = v.w * 0.125f;
    }

    float m[4], l[4], acc[4][4];
#pragma unroll
    for (int i = 0; i < 4; i++) {
        m[i] = -1e30f; l[i] = 0.f;
#pragma unroll
        for (int j = 0; j < 4; j++) acc[i][j] = 0.f;
    }

    for (int kt = 0; kt <= qt; kt++) {
        const int k0 = kt << 6;
        __syncthreads();
        for (int i = tid; i < 64 * 16; i += 256) {
            int r = i >> 4, c4 = (i & 15) << 2;
            size_t g = ((((size_t)b * T_ + k0 + r) * H_ + h) << 6) + c4;
            float4 kv = *(const float4*)&g_k[g];
            float4 vv = *(const float4*)&g_v[g];
            float* kd = &Ks[r * 65 + c4];
            kd[0] = kv.x; kd[1] = kv.y; kd[2] = kv.z; kd[3] = kv.w;
            float* vd = &Vs[r * 65 + c4];
            vd[0] = vv.x; vd[1] = vv.y; vd[2] = vv.z; vd[3] = vv.w;
        }
        __syncthreads();

        float s[4][4];
#pragma unroll
        for (int i = 0; i < 4; i++)
#pragma unroll
            for (int j = 0; j < 4; j++) s[i][j] = 0.f;
#pragma unroll 8
        for (int d = 0; d < 64; d++) {
            float a[4], bb[4];
#pragma unroll
            for (int i = 0; i < 4; i++) a[i]  = Qs[(ty + (i << 4)) * 65 + d];
#pragma unroll
            for (int j = 0; j < 4; j++) bb[j] = Ks[(tx + (j << 4)) * 65 + d];
#pragma unroll
            for (int i = 0; i < 4; i++)
#pragma unroll
                for (int j = 0; j < 4; j++)
                    s[i][j] = fmaf(a[i], bb[j], s[i][j]);
        }

        if (kt == qt) {
#pragma unroll
            for (int i = 0; i < 4; i++)
#pragma unroll
                for (int j = 0; j < 4; j++)
                    if ((tx + (j << 4)) > (ty + (i << 4))) s[i][j] = -1e30f;
        }

#pragma unroll
        for (int i = 0; i < 4; i++) {
            float mt = fmaxf(fmaxf(s[i][0], s[i][1]), fmaxf(s[i][2], s[i][3]));
#pragma unroll
            for (int o = 8; o >= 1; o >>= 1)
                mt = fmaxf(mt, __shfl_xor_sync(0xffffffffu, mt, o));
            float mn = fmaxf(m[i], mt);
            float al = __expf(m[i] - mn);
            m[i] = mn;
            float rs = 0.f;
#pragma unroll
            for (int j = 0; j < 4; j++) {
                float p = __expf(s[i][j] - mn);
                rs += p;
                Ps[(ty + (i << 4)) * 65 + tx + (j << 4)] = p;
            }
#pragma unroll
            for (int o = 8; o >= 1; o >>= 1)
                rs += __shfl_xor_sync(0xffffffffu, rs, o);
            l[i] = l[i] * al + rs;
#pragma unroll
            for (int j = 0; j < 4; j++) acc[i][j] *= al;
        }
        __syncthreads();

#pragma unroll 4
        for (int jj = 0; jj < 64; jj++) {
            float pv[4], vv[4];
#pragma unroll
            for (int i = 0; i < 4; i++) pv[i] = Ps[(ty + (i << 4)) * 65 + jj];
#pragma unroll
            for (int j = 0; j < 4; j++) vv[j] = Vs[jj * 65 + tx + (j << 4)];
#pragma unroll
            for (int i = 0; i < 4; i++)
#pragma unroll
                for (int j = 0; j < 4; j++)
                    acc[i][j] = fmaf(pv[i], vv[j], acc[i][j]);
        }
    }

#pragma unroll
    for (int i = 0; i < 4; i++) {
        float inv = 1.f / l[i];
#pragma unroll
        for (int j = 0; j < 4; j++) {
            int r = ty + (i << 4), c = tx + (j << 4);
            g_y[((((size_t)b * T_ + q0 + r) * H_ + h) << 6) + c] = acc[i][j] * inv;
        }
    }
}

// ============================================================
// launch
// ============================================================
extern "C" void kernel_launch(void* const* d_in, const int* in_sizes, int n_in,
                              void* d_out, int out_size)
{
    const float* x   = (const float*)d_in[0];
    const float* Wq  = (const float*)d_in[1];
    const float* Wk  = (const float*)d_in[2];
    const float* Wv  = (const float*)d_in[3];
    const float* Wku = (const float*)d_in[4];
    const float* Wvu = (const float*)d_in[5];
    const float* Wc  = (const float*)d_in[6];

    float* out      = (float*)d_out;
    float* y_out    = out;
    float* klat_out = out + Y_ELEMS;
    float* vlat_out = out + Y_ELEMS + KL_ELEMS;

    float *qp, *yp;
    __nv_bfloat16 *xh, *xl, *yh, *yl, *wh, *wl;
    cudaGetSymbolAddress((void**)&qp, g_q);
    cudaGetSymbolAddress((void**)&yp, g_y);
    cudaGetSymbolAddress((void**)&xh, g_xh);
    cudaGetSymbolAddress((void**)&xl, g_xl);
    cudaGetSymbolAddress((void**)&yh, g_yh);
    cudaGetSymbolAddress((void**)&yl, g_yl);
    cudaGetSymbolAddress((void**)&wh, g_wh);
    cudaGetSymbolAddress((void**)&wl, g_wl);

    cudaFuncSetAttribute(attn_kernel, cudaFuncAttributeMaxDynamicSharedMemorySize, ATT_SMEM);
    cudaFuncSetAttribute(hgemm_nt, cudaFuncAttributeMaxDynamicSharedMemorySize, GS_SMEM);
    cudaFuncSetAttribute(hgemm_kv, cudaFuncAttributeMaxDynamicSharedMemorySize, GS_SMEM);

    // 1. rope tables
    rope_table_kernel<<<T_, 64>>>();

    // 2. split x and weights into bf16 hi/lo
    split_bf16_kernel<<<(B_*T_*CDIM/4 + 255)/256, 256>>>(x,  xh, xl, B_*T_*CDIM/4);
    split_bf16_kernel<<<(1024*1024/4 + 255)/256, 256>>>(Wq, wh + WQ_OFF, wl + WQ_OFF, 1024*1024/4);
    split_bf16_kernel<<<(512*1024/4  + 255)/256, 256>>>(Wk, wh + WK_OFF, wl + WK_OFF, 512*1024/4);
    split_bf16_kernel<<<(512*1024/4  + 255)/256, 256>>>(Wv, wh + WV_OFF, wl + WV_OFF, 512*1024/4);
    split_bf16_kernel<<<(1024*1024/4 + 255)/256, 256>>>(Wc, wh + WC_OFF, wl + WC_OFF, 1024*1024/4);

    // 3. HMMA GEMMs: q, then fused k_lat/v_lat
    dim3 gq(CDIM / 128, (B_ * T_) / 128);
    hgemm_nt<<<gq, 256, GS_SMEM>>>(xh, xl, wh + WQ_OFF, wl + WQ_OFF, qp, CDIM, CDIM);
    dim3 gkv(512 / 128, (B_ * T_) / 128, 2);
    hgemm_kv<<<gkv, 256, GS_SMEM>>>(xh, xl,
                                    wh + WK_OFF, wl + WK_OFF,
                                    wh + WV_OFF, wl + WV_OFF,
                                    klat_out, vlat_out, CDIM, 512);

    // 4. up-project + RoPE
    upproj_rope_kernel<<<B_ * T_, 256>>>(klat_out, vlat_out, Wku, Wvu);

    // 5. causal flash attention -> g_y
    dim3 ga(T_ / 64, H_, B_);
    attn_kernel<<<ga, 256, ATT_SMEM>>>();

    // 6. y = attn @ Wc^T via HMMA
    split_bf16_kernel<<<(B_*T_*CDIM/4 + 255)/256, 256>>>(yp, yh, yl, B_*T_*CDIM/4);
    hgemm_nt<<<gq, 256, GS_SMEM>>>(yh, yl, wh + WC_OFF, wl + WC_OFF, y_out, CDIM, CDIM);
}

// round 4
// speedup vs baseline: 2.4812x; 1.8803x over previous
#include <cuda_runtime.h>
#include <cuda_bf16.h>
#include <math.h>
#include <stdint.h>

#define B_   2
#define T_   2048
#define H_   16
#define DH   64
#define DL   32
#define CDIM 1024

#define Y_ELEMS  ((size_t)B_*T_*CDIM)          // 4194304
#define KL_ELEMS ((size_t)B_*T_*H_*DL)         // 2097152

// ---- scratch (device globals; no allocation allowed) ----
__device__ float g_q[(size_t)B_*T_*H_*DH];     // fp32 q from GEMM
__device__ float g_cos[T_*DH];
__device__ float g_sin[T_*DH];

// bf16 split-precision buffers
__device__ __nv_bfloat16 g_xh[(size_t)B_*T_*CDIM];
__device__ __nv_bfloat16 g_xl[(size_t)B_*T_*CDIM];
__device__ __nv_bfloat16 g_yh[(size_t)B_*T_*CDIM];   // attention out hi
__device__ __nv_bfloat16 g_yl[(size_t)B_*T_*CDIM];   // attention out lo
__device__ __nv_bfloat16 g_qh[(size_t)B_*T_*H_*DH];
__device__ __nv_bfloat16 g_ql[(size_t)B_*T_*H_*DH];
__device__ __nv_bfloat16 g_kh[(size_t)B_*T_*H_*DH];
__device__ __nv_bfloat16 g_kl[(size_t)B_*T_*H_*DH];
__device__ __nv_bfloat16 g_vh[(size_t)B_*T_*H_*DH];
__device__ __nv_bfloat16 g_vl[(size_t)B_*T_*H_*DH];
// weights packed: Wq @0 (1M), Wk @1M (0.5M), Wv @1.5M (0.5M), Wc @2M (1M)
__device__ __nv_bfloat16 g_wh[3u*1024*1024];
__device__ __nv_bfloat16 g_wl[3u*1024*1024];
#define WQ_OFF 0u
#define WK_OFF (1024u*1024u)
#define WV_OFF (1536u*1024u)
#define WC_OFF (2048u*1024u)

// ============================================================
// PTX helpers
// ============================================================
__device__ __forceinline__ uint32_t smem_u32(const void* p) {
    uint32_t a;
    asm("{ .reg .u64 t; cvta.to.shared.u64 t, %1; cvt.u32.u64 %0, t; }"
        : "=r"(a) : "l"(p));
    return a;
}
__device__ __forceinline__ void cp16(uint32_t dst, const void* src) {
    asm volatile("cp.async.cg.shared.global [%0], [%1], 16;\n"
                 :: "r"(dst), "l"(src));
}
__device__ __forceinline__ void cp_commit() {
    asm volatile("cp.async.commit_group;\n" ::: "memory");
}
template<int N> __device__ __forceinline__ void cp_wait() {
    asm volatile("cp.async.wait_group %0;\n" :: "n"(N) : "memory");
}
__device__ __forceinline__ void ldm_x4(uint32_t* r, uint32_t addr) {
    asm volatile("ldmatrix.sync.aligned.m8n8.x4.shared.b16 {%0,%1,%2,%3}, [%4];"
        : "=r"(r[0]), "=r"(r[1]), "=r"(r[2]), "=r"(r[3]) : "r"(addr));
}
__device__ __forceinline__ void ldm_x4_t(uint32_t* r, uint32_t addr) {
    asm volatile("ldmatrix.sync.aligned.m8n8.x4.trans.shared.b16 {%0,%1,%2,%3}, [%4];"
        : "=r"(r[0]), "=r"(r[1]), "=r"(r[2]), "=r"(r[3]) : "r"(addr));
}
__device__ __forceinline__ void mma_bf16(float* c, const uint32_t* a, const uint32_t* b) {
    asm volatile("mma.sync.aligned.m16n8k16.row.col.f32.bf16.bf16.f32 "
        "{%0,%1,%2,%3}, {%4,%5,%6,%7}, {%8,%9}, {%0,%1,%2,%3};\n"
        : "+f"(c[0]), "+f"(c[1]), "+f"(c[2]), "+f"(c[3])
        : "r"(a[0]), "r"(a[1]), "r"(a[2]), "r"(a[3]), "r"(b[0]), "r"(b[1]));
}
// split two floats into packed bf16x2 hi + bf16x2 lo(residual)
__device__ __forceinline__ void split2(float a, float b, uint32_t& h, uint32_t& l) {
    __nv_bfloat16 ha = __float2bfloat16(a), hb = __float2bfloat16(b);
    __nv_bfloat16 la = __float2bfloat16(a - __bfloat162float(ha));
    __nv_bfloat16 lb = __float2bfloat16(b - __bfloat162float(hb));
    h = (uint32_t)__bfloat16_as_ushort(ha) | ((uint32_t)__bfloat16_as_ushort(hb) << 16);
    l = (uint32_t)__bfloat16_as_ushort(la) | ((uint32_t)__bfloat16_as_ushort(lb) << 16);
}

// ============================================================
// fp32 -> (bf16 hi, bf16 lo) split kernel
// ============================================================
__global__ void __launch_bounds__(256)
split_bf16_kernel(const float* __restrict__ in,
                  __nv_bfloat16* __restrict__ hi,
                  __nv_bfloat16* __restrict__ lo, int n4)
{
    int i = blockIdx.x * blockDim.x + threadIdx.x;
    if (i >= n4) return;
    float4 v = ((const float4*)in)[i];
    uint32_t h0, l0, h1, l1;
    split2(v.x, v.y, h0, l0);
    split2(v.z, v.w, h1, l1);
    ((uint32_t*)hi)[2*i]   = h0;
    ((uint32_t*)hi)[2*i+1] = h1;
    ((uint32_t*)lo)[2*i]   = l0;
    ((uint32_t*)lo)[2*i+1] = l1;
}

// ============================================================
// HMMA GEMM (validated R3): C = A @ W^T, split-bf16 3-MMA
// ============================================================
#define GS_ROWB   80
#define GS_MAT    (128 * GS_ROWB)
#define GS_STAGE  (4 * GS_MAT)
#define GS_SMEM   (2 * GS_STAGE)

__device__ __forceinline__ void hgemm_load_chunk(
    const __nv_bfloat16* __restrict__ Ah, const __nv_bfloat16* __restrict__ Al,
    const __nv_bfloat16* __restrict__ Bh, const __nv_bfloat16* __restrict__ Bl,
    int K, int bm, int bn, int k0, uint32_t sbase, int tid)
{
#pragma unroll
    for (int i = 0; i < 8; i++) {
        int task = tid + (i << 8);
        int op   = task >> 9;
        int t2   = task & 511;
        int row  = t2 >> 2;
        int g    = t2 & 3;
        const __nv_bfloat16* base;
        int grow;
        if      (op == 0) { base = Ah; grow = bm + row; }
        else if (op == 1) { base = Al; grow = bm + row; }
        else if (op == 2) { base = Bh; grow = bn + row; }
        else              { base = Bl; grow = bn + row; }
        const void* src = base + (size_t)grow * K + k0 + (g << 3);
        uint32_t dst = sbase + op * GS_MAT + row * GS_ROWB + (g << 4);
        cp16(dst, src);
    }
}

__device__ __forceinline__ void hgemm_body(
    const __nv_bfloat16* __restrict__ Ah, const __nv_bfloat16* __restrict__ Al,
    const __nv_bfloat16* __restrict__ Bh, const __nv_bfloat16* __restrict__ Bl,
    float* __restrict__ C, int K, int N)
{
    extern __shared__ __align__(128) char sm[];
    const uint32_t smb = smem_u32(sm);
    const int tid  = threadIdx.x;
    const int wid  = tid >> 5;
    const int lane = tid & 31;
    const int bm = blockIdx.y << 7;
    const int bn = blockIdx.x << 7;
    const int wm = (wid >> 2) << 6;
    const int wn = (wid & 3) << 5;

    const int rA = (lane & 7) + ((lane >> 3) & 1) * 8;
    const int cA = (lane >> 4) << 3;
    const int rB = (lane & 7) + ((lane >> 4) << 3);
    const int cB = ((lane >> 3) & 1) << 3;

    float acc[4][4][4];
#pragma unroll
    for (int mt = 0; mt < 4; mt++)
#pragma unroll
        for (int nt = 0; nt < 4; nt++)
#pragma unroll
            for (int e = 0; e < 4; e++) acc[mt][nt][e] = 0.f;

    const int NC = K >> 5;

    hgemm_load_chunk(Ah, Al, Bh, Bl, K, bm, bn, 0, smb, tid);
    cp_commit();
    hgemm_load_chunk(Ah, Al, Bh, Bl, K, bm, bn, 32, smb + GS_STAGE, tid);
    cp_commit();

    for (int c = 0; c < NC; c++) {
        const uint32_t sb = smb + (c & 1) * GS_STAGE;
        if (c + 1 < NC) cp_wait<1>(); else cp_wait<0>();
        __syncthreads();

#pragma unroll
        for (int ks = 0; ks < 2; ks++) {
            const int k0 = ks << 4;
            uint32_t ah[4][4], al[4][4], bh[2][4], bl[2][4];
#pragma unroll
            for (int mt = 0; mt < 4; mt++) {
                uint32_t ro = (uint32_t)(wm + (mt << 4) + rA) * GS_ROWB + ((k0 + cA) << 1);
                ldm_x4(ah[mt], sb + 0 * GS_MAT + ro);
                ldm_x4(al[mt], sb + 1 * GS_MAT + ro);
            }
#pragma unroll
            for (int nt2 = 0; nt2 < 2; nt2++) {
                uint32_t ro = (uint32_t)(wn + (nt2 << 4) + rB) * GS_ROWB + ((k0 + cB) << 1);
                ldm_x4(bh[nt2], sb + 2 * GS_MAT + ro);
                ldm_x4(bl[nt2], sb + 3 * GS_MAT + ro);
            }
#pragma unroll
            for (int mt = 0; mt < 4; mt++)
#pragma unroll
                for (int nt = 0; nt < 4; nt++) {
                    const uint32_t* bhp = &bh[nt >> 1][(nt & 1) << 1];
                    const uint32_t* blp = &bl[nt >> 1][(nt & 1) << 1];
                    mma_bf16(acc[mt][nt], ah[mt], bhp);
                    mma_bf16(acc[mt][nt], ah[mt], blp);
                    mma_bf16(acc[mt][nt], al[mt], bhp);
                }
        }
        __syncthreads();
        if (c + 2 < NC) {
            hgemm_load_chunk(Ah, Al, Bh, Bl, K, bm, bn, (c + 2) << 5,
                             smb + (c & 1) * GS_STAGE, tid);
        }
        cp_commit();
    }

    const int g  = lane >> 2;
    const int tg = lane & 3;
#pragma unroll
    for (int mt = 0; mt < 4; mt++) {
        const int row0 = bm + wm + (mt << 4) + g;
#pragma unroll
        for (int nt = 0; nt < 4; nt++) {
            const int col = bn + wn + (nt << 3) + (tg << 1);
            *(float2*)&C[(size_t)row0 * N + col] =
                make_float2(acc[mt][nt][0], acc[mt][nt][1]);
            *(float2*)&C[(size_t)(row0 + 8) * N + col] =
                make_float2(acc[mt][nt][2], acc[mt][nt][3]);
        }
    }
}

__global__ void __launch_bounds__(256, 1)
hgemm_nt(const __nv_bfloat16* __restrict__ Ah, const __nv_bfloat16* __restrict__ Al,
         const __nv_bfloat16* __restrict__ Bh, const __nv_bfloat16* __restrict__ Bl,
         float* __restrict__ C, int K, int N)
{
    hgemm_body(Ah, Al, Bh, Bl, C, K, N);
}

__global__ void __launch_bounds__(256, 1)
hgemm_kv(const __nv_bfloat16* __restrict__ Ah, const __nv_bfloat16* __restrict__ Al,
         const __nv_bfloat16* __restrict__ Bkh, const __nv_bfloat16* __restrict__ Bkl,
         const __nv_bfloat16* __restrict__ Bvh, const __nv_bfloat16* __restrict__ Bvl,
         float* __restrict__ Ck, float* __restrict__ Cv, int K, int N)
{
    if (blockIdx.z) hgemm_body(Ah, Al, Bvh, Bvl, Cv, K, N);
    else            hgemm_body(Ah, Al, Bkh, Bkl, Ck, K, N);
}

// ============================================================
// RoPE table
// ============================================================
__global__ void rope_table_kernel() {
    int t = blockIdx.x;
    int c = threadIdx.x;
    int j = c & 31;
    double inv = pow(10000.0, -(double)j / 32.0);
    float  ang = (float)t * (float)inv;
    double s, cc;
    sincos((double)ang, &s, &cc);
    g_cos[t * DH + c] = (float)cc;
    g_sin[t * DH + c] = (float)s;
}

// ============================================================
// Up-projection + RoPE, emits bf16 hi/lo q (scaled), k, v
// ============================================================
__global__ void __launch_bounds__(256)
upproj_rope_kernel(const float* __restrict__ klat, const float* __restrict__ vlat,
                   const float* __restrict__ Wku,  const float* __restrict__ Wvu)
{
    const int bt = blockIdx.x;
    const int t  = bt & (T_ - 1);
    __shared__ float skl[512], svl[512];
    __shared__ float swk[64 * 33], swv[64 * 33];
    const int tid = threadIdx.x;

    skl[tid]       = klat[(size_t)bt * 512 + tid];
    skl[tid + 256] = klat[(size_t)bt * 512 + tid + 256];
    svl[tid]       = vlat[(size_t)bt * 512 + tid];
    svl[tid + 256] = vlat[(size_t)bt * 512 + tid + 256];
    for (int i = tid; i < 64 * 32; i += 256) {
        int d = i >> 5, l = i & 31;
        swk[d * 33 + l] = Wku[i];
        swv[d * 33 + l] = Wvu[i];
    }
    __syncthreads();

#pragma unroll
    for (int p = tid; p < 512; p += 256) {
        const int h  = p >> 5, i = p & 31;
        const int d0 = i << 1, d1 = d0 + 1;
        const float* kl  = &skl[h << 5];
        const float* vl  = &svl[h << 5];
        const float* wk0 = &swk[d0 * 33];
        const float* wk1 = &swk[d1 * 33];
        const float* wv0 = &swv[d0 * 33];
        const float* wv1 = &swv[d1 * 33];
        float k0 = 0.f, k1 = 0.f, v0 = 0.f, v1 = 0.f;
#pragma unroll
        for (int l = 0; l < 32; l++) {
            float klv = kl[l], vlv = vl[l];
            k0 = fmaf(klv, wk0[l], k0);
            k1 = fmaf(klv, wk1[l], k1);
            v0 = fmaf(vlv, wv0[l], v0);
            v1 = fmaf(vlv, wv1[l], v1);
        }
        const float c0 = g_cos[t * DH + d0], s0 = g_sin[t * DH + d0];
        const float c1 = g_cos[t * DH + d1], s1 = g_sin[t * DH + d1];
        const size_t gi = ((size_t)bt * H_ + h) * DH;
        const size_t pi = (gi + d0) >> 1;          // bf16x2 pair index

        uint32_t hw, lw;
        // rope(k)
        split2(k0 * c0 - k1 * s0, k1 * c1 + k0 * s1, hw, lw);
        ((uint32_t*)g_kh)[pi] = hw; ((uint32_t*)g_kl)[pi] = lw;
        // v
        split2(v0, v1, hw, lw);
        ((uint32_t*)g_vh)[pi] = hw; ((uint32_t*)g_vl)[pi] = lw;
        // rope(q), pre-scaled by 1/sqrt(64)
        float q0v = g_q[gi + d0] * 0.125f, q1v = g_q[gi + d1] * 0.125f;
        split2(q0v * c0 - q1v * s0, q1v * c1 + q0v * s1, hw, lw);
        ((uint32_t*)g_qh)[pi] = hw; ((uint32_t*)g_ql)[pi] = lw;
    }
}

// ============================================================
// HMMA causal flash attention, split-bf16 3-MMA both GEMMs.
// CTA: 128 q rows, 8 warps x 16 rows. K-blocks of 64.
// smem rows padded to 144B -> conflict-free ldmatrix (36-word stride).
// ============================================================
#define AT_ROWB   144
#define AT_MAT    (64 * AT_ROWB)        // 9216
#define AT_STAGE  (4 * AT_MAT)          // 36864 (Kh,Kl,Vh,Vl)
#define AT_Q      (2 * AT_STAGE)        // 73728
#define AT_QMAT   (128 * AT_ROWB)       // 18432
#define AT_SMEM   (AT_Q + 2 * AT_QMAT)  // 110592

__device__ __forceinline__ void attn_load_kv(int b, int h, int kb,
                                             uint32_t sbase, int tid)
{
    const int k0 = kb << 6;
#pragma unroll
    for (int i = 0; i < 8; i++) {
        int task = tid + (i << 8);     // 2048: op(4) x row(64) x granule(8)
        int op = task >> 9;
        int t2 = task & 511;
        int row = t2 >> 3, g = t2 & 7;
        const __nv_bfloat16* base =
            (op == 0) ? g_kh : (op == 1) ? g_kl : (op == 2) ? g_vh : g_vl;
        const void* src = base + ((size_t)(b * T_ + k0 + row) * H_ + h) * DH + (g << 3);
        cp16(sbase + op * AT_MAT + row * AT_ROWB + (g << 4), src);
    }
}

__global__ void __launch_bounds__(256, 1)
attn_mma_kernel()
{
    extern __shared__ __align__(128) char sm[];
    const uint32_t smb = smem_u32(sm);
    const int tid = threadIdx.x;
    const int wid = tid >> 5, lane = tid & 31;
    const int qt = gridDim.x - 1 - blockIdx.x;   // heavy blocks first
    const int h = blockIdx.y, b = blockIdx.z;
    const int q0 = qt << 7;
    const int nkb = 2 * qt + 2;
    const int g = lane >> 2, tg = lane & 3;

    // Q tile load (group 0): hi/lo, 128 rows x 8 granules x 2
#pragma unroll
    for (int i = 0; i < 8; i++) {
        int task = tid + (i << 8);
        int op = task >> 10, t2 = task & 1023;
        int row = t2 >> 3, gg = t2 & 7;
        const __nv_bfloat16* base = op ? g_ql : g_qh;
        const void* src = base + ((size_t)(b * T_ + q0 + row) * H_ + h) * DH + (gg << 3);
        cp16(smb + AT_Q + op * AT_QMAT + row * AT_ROWB + (gg << 4), src);
    }
    cp_commit();
    attn_load_kv(b, h, 0, smb, tid);
    cp_commit();
    if (nkb > 1) attn_load_kv(b, h, 1, smb + AT_STAGE, tid);
    cp_commit();

    cp_wait<2>();
    __syncthreads();

    // Q fragments (persistent)
    const int rA = (lane & 7) + ((lane >> 3) & 1) * 8;
    const int cA = (lane >> 4) << 3;
    uint32_t qh[4][4], ql[4][4];
#pragma unroll
    for (int kf = 0; kf < 4; kf++) {
        uint32_t ro = (uint32_t)(wid * 16 + rA) * AT_ROWB + ((kf * 16 + cA) << 1);
        ldm_x4(qh[kf], smb + AT_Q + ro);
        ldm_x4(ql[kf], smb + AT_Q + AT_QMAT + ro);
    }

    const int rB = (lane & 7) + ((lane >> 4) << 3);
    const int cB = ((lane >> 3) & 1) << 3;
    const int rV = lane & 15;
    const int cV = (lane >> 4) << 4;

    float yacc[8][4];
#pragma unroll
    for (int i = 0; i < 8; i++)
#pragma unroll
        for (int e = 0; e < 4; e++) yacc[i][e] = 0.f;
    float m0 = -1e30f, m1 = -1e30f, l0 = 0.f, l1 = 0.f;

    for (int kb = 0; kb < nkb; kb++) {
        const uint32_t sb = smb + (kb & 1) * AT_STAGE;
        if (kb + 1 < nkb) cp_wait<1>(); else cp_wait<0>();
        __syncthreads();

        // ---- S = Q K^T (3-MMA split) ----
        float s[8][4];
#pragma unroll
        for (int i = 0; i < 8; i++)
#pragma unroll
            for (int e = 0; e < 4; e++) s[i][e] = 0.f;
#pragma unroll
        for (int kf = 0; kf < 4; kf++) {
#pragma unroll
            for (int nt16 = 0; nt16 < 4; nt16++) {
                uint32_t ro = (uint32_t)(nt16 * 16 + rB) * AT_ROWB + ((kf * 16 + cB) << 1);
                uint32_t bh[4], bl[4];
                ldm_x4(bh, sb + 0 * AT_MAT + ro);
                ldm_x4(bl, sb + 1 * AT_MAT + ro);
#pragma unroll
                for (int hf = 0; hf < 2; hf++) {
                    float* sp = s[nt16 * 2 + hf];
                    mma_bf16(sp, qh[kf], &bh[hf * 2]);
                    mma_bf16(sp, qh[kf], &bl[hf * 2]);
                    mma_bf16(sp, ql[kf], &bh[hf * 2]);
                }
            }
        }

        // ---- causal mask (diagonal blocks only) ----
        if (kb >= 2 * qt) {
            const int row0 = q0 + wid * 16 + g;
#pragma unroll
            for (int nt = 0; nt < 8; nt++) {
                const int col0 = (kb << 6) + nt * 8 + (tg << 1);
                if (col0     > row0)     s[nt][0] = -1e30f;
                if (col0 + 1 > row0)     s[nt][1] = -1e30f;
                if (col0     > row0 + 8) s[nt][2] = -1e30f;
                if (col0 + 1 > row0 + 8) s[nt][3] = -1e30f;
            }
        }

        // ---- online softmax (fp32) ----
        float mx0 = -1e30f, mx1 = -1e30f;
#pragma unroll
        for (int nt = 0; nt < 8; nt++) {
            mx0 = fmaxf(mx0, fmaxf(s[nt][0], s[nt][1]));
            mx1 = fmaxf(mx1, fmaxf(s[nt][2], s[nt][3]));
        }
        mx0 = fmaxf(mx0, __shfl_xor_sync(0xffffffffu, mx0, 1));
        mx0 = fmaxf(mx0, __shfl_xor_sync(0xffffffffu, mx0, 2));
        mx1 = fmaxf(mx1, __shfl_xor_sync(0xffffffffu, mx1, 1));
        mx1 = fmaxf(mx1, __shfl_xor_sync(0xffffffffu, mx1, 2));
        const float mn0 = fmaxf(m0, mx0), mn1 = fmaxf(m1, mx1);
        const float a0 = __expf(m0 - mn0), a1 = __expf(m1 - mn1);
        m0 = mn0; m1 = mn1;
        float r0 = 0.f, r1 = 0.f;
#pragma unroll
        for (int nt = 0; nt < 8; nt++) {
            s[nt][0] = __expf(s[nt][0] - mn0);
            s[nt][1] = __expf(s[nt][1] - mn0);
            s[nt][2] = __expf(s[nt][2] - mn1);
            s[nt][3] = __expf(s[nt][3] - mn1);
            r0 += s[nt][0] + s[nt][1];
            r1 += s[nt][2] + s[nt][3];
        }
        r0 += __shfl_xor_sync(0xffffffffu, r0, 1);
        r0 += __shfl_xor_sync(0xffffffffu, r0, 2);
        r1 += __shfl_xor_sync(0xffffffffu, r1, 1);
        r1 += __shfl_xor_sync(0xffffffffu, r1, 2);
        l0 = l0 * a0 + r0;
        l1 = l1 * a1 + r1;
#pragma unroll
        for (int i = 0; i < 8; i++) {
            yacc[i][0] *= a0; yacc[i][1] *= a0;
            yacc[i][2] *= a1; yacc[i][3] *= a1;
        }

        // ---- O += P V (3-MMA split; P stays in registers) ----
#pragma unroll
        for (int kf = 0; kf < 4; kf++) {
            uint32_t ph[4], pl[4];
            split2(s[2*kf][0],   s[2*kf][1],   ph[0], pl[0]);
            split2(s[2*kf][2],   s[2*kf][3],   ph[1], pl[1]);
            split2(s[2*kf+1][0], s[2*kf+1][1], ph[2], pl[2]);
            split2(s[2*kf+1][2], s[2*kf+1][3], ph[3], pl[3]);
#pragma unroll
            for (int dt = 0; dt < 4; dt++) {
                uint32_t vh[4], vl[4];
                uint32_t ro = (uint32_t)(kf * 16 + rV) * AT_ROWB + dt * 32 + cV;
                ldm_x4_t(vh, sb + 2 * AT_MAT + ro);
                ldm_x4_t(vl, sb + 3 * AT_MAT + ro);
#pragma unroll
                for (int hf = 0; hf < 2; hf++) {
                    float* yp2 = yacc[dt * 2 + hf];
                    mma_bf16(yp2, ph, &vh[hf * 2]);
                    mma_bf16(yp2, ph, &vl[hf * 2]);
                    mma_bf16(yp2, pl, &vh[hf * 2]);
                }
            }
        }

        __syncthreads();
        if (kb + 2 < nkb)
            attn_load_kv(b, h, kb + 2, smb + (kb & 1) * AT_STAGE, tid);
        cp_commit();
    }

    // ---- epilogue: y/l, write bf16 hi/lo directly for Wc GEMM ----
    const float il0 = 1.f / l0, il1 = 1.f / l1;
    const int row0 = q0 + wid * 16 + g;
#pragma unroll
    for (int dt8 = 0; dt8 < 8; dt8++) {
        const int col = h * 64 + dt8 * 8 + (tg << 1);
        uint32_t hw, lw;
        split2(yacc[dt8][0] * il0, yacc[dt8][1] * il0, hw, lw);
        size_t o0 = ((size_t)(b * T_ + row0) * CDIM + col) >> 1;
        ((uint32_t*)g_yh)[o0] = hw; ((uint32_t*)g_yl)[o0] = lw;
        split2(yacc[dt8][2] * il1, yacc[dt8][3] * il1, hw, lw);
        size_t o1 = ((size_t)(b * T_ + row0 + 8) * CDIM + col) >> 1;
        ((uint32_t*)g_yh)[o1] = hw; ((uint32_t*)g_yl)[o1] = lw;
    }
}

// ============================================================
// launch
// ============================================================
extern "C" void kernel_launch(void* const* d_in, const int* in_sizes, int n_in,
                              void* d_out, int out_size)
{
    const float* x   = (const float*)d_in[0];
    const float* Wq  = (const float*)d_in[1];
    const float* Wk  = (const float*)d_in[2];
    const float* Wv  = (const float*)d_in[3];
    const float* Wku = (const float*)d_in[4];
    const float* Wvu = (const float*)d_in[5];
    const float* Wc  = (const float*)d_in[6];

    float* out      = (float*)d_out;
    float* y_out    = out;
    float* klat_out = out + Y_ELEMS;
    float* vlat_out = out + Y_ELEMS + KL_ELEMS;

    float *qp;
    __nv_bfloat16 *xh, *xl, *yh, *yl, *wh, *wl;
    cudaGetSymbolAddress((void**)&qp, g_q);
    cudaGetSymbolAddress((void**)&xh, g_xh);
    cudaGetSymbolAddress((void**)&xl, g_xl);
    cudaGetSymbolAddress((void**)&yh, g_yh);
    cudaGetSymbolAddress((void**)&yl, g_yl);
    cudaGetSymbolAddress((void**)&wh, g_wh);
    cudaGetSymbolAddress((void**)&wl, g_wl);

    cudaFuncSetAttribute(attn_mma_kernel, cudaFuncAttributeMaxDynamicSharedMemorySize, AT_SMEM);
    cudaFuncSetAttribute(hgemm_nt, cudaFuncAttributeMaxDynamicSharedMemorySize, GS_SMEM);
    cudaFuncSetAttribute(hgemm_kv, cudaFuncAttributeMaxDynamicSharedMemorySize, GS_SMEM);

    // 1. rope tables
    rope_table_kernel<<<T_, 64>>>();

    // 2. split x and weights into bf16 hi/lo
    split_bf16_kernel<<<(B_*T_*CDIM/4 + 255)/256, 256>>>(x,  xh, xl, B_*T_*CDIM/4);
    split_bf16_kernel<<<(1024*1024/4 + 255)/256, 256>>>(Wq, wh + WQ_OFF, wl + WQ_OFF, 1024*1024/4);
    split_bf16_kernel<<<(512*1024/4  + 255)/256, 256>>>(Wk, wh + WK_OFF, wl + WK_OFF, 512*1024/4);
    split_bf16_kernel<<<(512*1024/4  + 255)/256, 256>>>(Wv, wh + WV_OFF, wl + WV_OFF, 512*1024/4);
    split_bf16_kernel<<<(1024*1024/4 + 255)/256, 256>>>(Wc, wh + WC_OFF, wl + WC_OFF, 1024*1024/4);

    // 3. HMMA GEMMs: q, fused k_lat/v_lat
    dim3 gq(CDIM / 128, (B_ * T_) / 128);
    hgemm_nt<<<gq, 256, GS_SMEM>>>(xh, xl, wh + WQ_OFF, wl + WQ_OFF, qp, CDIM, CDIM);
    dim3 gkv(512 / 128, (B_ * T_) / 128, 2);
    hgemm_kv<<<gkv, 256, GS_SMEM>>>(xh, xl,
                                    wh + WK_OFF, wl + WK_OFF,
                                    wh + WV_OFF, wl + WV_OFF,
                                    klat_out, vlat_out, CDIM, 512);

    // 4. up-project + RoPE -> bf16 hi/lo q,k,v
    upproj_rope_kernel<<<B_ * T_, 256>>>(klat_out, vlat_out, Wku, Wvu);

    // 5. HMMA causal flash attention -> g_yh/g_yl
    dim3 ga(T_ / 128, H_, B_);
    attn_mma_kernel<<<ga, 256, AT_SMEM>>>();

    // 6. y = attn @ Wc^T via HMMA (inputs already split)
    hgemm_nt<<<gq, 256, GS_SMEM>>>(yh, yl, wh + WC_OFF, wl + WC_OFF, y_out, CDIM, CDIM);
}

// round 5
// speedup vs baseline: 3.2163x; 1.2963x over previous
#include <cuda_runtime.h>
#include <cuda_bf16.h>
#include <cuda_fp16.h>
#include <math.h>
#include <stdint.h>

#define B_   2
#define T_   2048
#define H_   16
#define DH   64
#define DL   32
#define CDIM 1024

#define Y_ELEMS  ((size_t)B_*T_*CDIM)
#define KL_ELEMS ((size_t)B_*T_*H_*DL)

// ---- scratch ----
__device__ float g_cos[T_*DH];
__device__ float g_sin[T_*DH];

__device__ __nv_bfloat16 g_xh[(size_t)B_*T_*CDIM];
__device__ __nv_bfloat16 g_xl[(size_t)B_*T_*CDIM];
__device__ __nv_bfloat16 g_yh[(size_t)B_*T_*CDIM];
__device__ __nv_bfloat16 g_yl[(size_t)B_*T_*CDIM];
// fp16 attention operands
__device__ __half g_qf[(size_t)B_*T_*H_*DH];
__device__ __half g_kf[(size_t)B_*T_*H_*DH];
__device__ __half g_vf[(size_t)B_*T_*H_*DH];
// weights packed: Wq @0 (1M), Wk @1M (0.5M), Wv @1.5M (0.5M), Wc @2M (1M)
__device__ __nv_bfloat16 g_wh[3u*1024*1024];
__device__ __nv_bfloat16 g_wl[3u*1024*1024];
#define WQ_OFF 0u
#define WK_OFF (1024u*1024u)
#define WV_OFF (1536u*1024u)
#define WC_OFF (2048u*1024u)

// ============================================================
// PTX helpers
// ============================================================
__device__ __forceinline__ uint32_t smem_u32(const void* p) {
    uint32_t a;
    asm("{ .reg .u64 t; cvta.to.shared.u64 t, %1; cvt.u32.u64 %0, t; }"
        : "=r"(a) : "l"(p));
    return a;
}
__device__ __forceinline__ void cp16(uint32_t dst, const void* src) {
    asm volatile("cp.async.cg.shared.global [%0], [%1], 16;\n"
                 :: "r"(dst), "l"(src));
}
__device__ __forceinline__ void cp_commit() {
    asm volatile("cp.async.commit_group;\n" ::: "memory");
}
template<int N> __device__ __forceinline__ void cp_wait() {
    asm volatile("cp.async.wait_group %0;\n" :: "n"(N) : "memory");
}
__device__ __forceinline__ void ldm_x4(uint32_t* r, uint32_t addr) {
    asm volatile("ldmatrix.sync.aligned.m8n8.x4.shared.b16 {%0,%1,%2,%3}, [%4];"
        : "=r"(r[0]), "=r"(r[1]), "=r"(r[2]), "=r"(r[3]) : "r"(addr));
}
__device__ __forceinline__ void ldm_x4_t(uint32_t* r, uint32_t addr) {
    asm volatile("ldmatrix.sync.aligned.m8n8.x4.trans.shared.b16 {%0,%1,%2,%3}, [%4];"
        : "=r"(r[0]), "=r"(r[1]), "=r"(r[2]), "=r"(r[3]) : "r"(addr));
}
__device__ __forceinline__ void mma_bf16(float* c, const uint32_t* a, const uint32_t* b) {
    asm volatile("mma.sync.aligned.m16n8k16.row.col.f32.bf16.bf16.f32 "
        "{%0,%1,%2,%3}, {%4,%5,%6,%7}, {%8,%9}, {%0,%1,%2,%3};\n"
        : "+f"(c[0]), "+f"(c[1]), "+f"(c[2]), "+f"(c[3])
        : "r"(a[0]), "r"(a[1]), "r"(a[2]), "r"(a[3]), "r"(b[0]), "r"(b[1]));
}
__device__ __forceinline__ void mma_f16(float* c, const uint32_t* a, const uint32_t* b) {
    asm volatile("mma.sync.aligned.m16n8k16.row.col.f32.f16.f16.f32 "
        "{%0,%1,%2,%3}, {%4,%5,%6,%7}, {%8,%9}, {%0,%1,%2,%3};\n"
        : "+f"(c[0]), "+f"(c[1]), "+f"(c[2]), "+f"(c[3])
        : "r"(a[0]), "r"(a[1]), "r"(a[2]), "r"(a[3]), "r"(b[0]), "r"(b[1]));
}
__device__ __forceinline__ void split2(float a, float b, uint32_t& h, uint32_t& l) {
    __nv_bfloat16 ha = __float2bfloat16(a), hb = __float2bfloat16(b);
    __nv_bfloat16 la = __float2bfloat16(a - __bfloat162float(ha));
    __nv_bfloat16 lb = __float2bfloat16(b - __bfloat162float(hb));
    h = (uint32_t)__bfloat16_as_ushort(ha) | ((uint32_t)__bfloat16_as_ushort(hb) << 16);
    l = (uint32_t)__bfloat16_as_ushort(la) | ((uint32_t)__bfloat16_as_ushort(lb) << 16);
}
__device__ __forceinline__ uint32_t pack_h2(float a, float b) {
    __half2 h = __floats2half2_rn(a, b);
    return *(uint32_t*)&h;
}

// ============================================================
// split kernels (fp32 -> bf16 hi/lo)
// ============================================================
__device__ __forceinline__ void split_store4(const float4 v,
                                             uint32_t* hi, uint32_t* lo, size_t i2)
{
    uint32_t h0, l0, h1, l1;
    split2(v.x, v.y, h0, l0);
    split2(v.z, v.w, h1, l1);
    hi[i2]   = h0; hi[i2+1] = h1;
    lo[i2]   = l0; lo[i2+1] = l1;
}

__global__ void __launch_bounds__(256)
split_x_kernel(const float* __restrict__ in)
{
    int i = blockIdx.x * blockDim.x + threadIdx.x;     // 1M granules of 4
    float4 v = ((const float4*)in)[i];
    split_store4(v, (uint32_t*)g_xh, (uint32_t*)g_xl, 2 * (size_t)i);
}

__global__ void __launch_bounds__(256)
split_w_kernel(const float* __restrict__ Wq, const float* __restrict__ Wk,
               const float* __restrict__ Wv, const float* __restrict__ Wc)
{
    int i = blockIdx.x * blockDim.x + threadIdx.x;     // 786432 granules
    const float* src; int off;
    if      (i < 262144) { src = Wq; off = i; }
    else if (i < 393216) { src = Wk; off = i - 262144; }
    else if (i < 524288) { src = Wv; off = i - 393216; }
    else                 { src = Wc; off = i - 524288; }
    float4 v = ((const float4*)src)[off];
    split_store4(v, (uint32_t*)g_wh, (uint32_t*)g_wl, 2 * (size_t)i);
}

// ============================================================
// HMMA GEMM (validated): C = A @ W^T, split-bf16 3-MMA.
// mode 0: fp32 store to C. mode 1: rope+scale -> g_qf (fp16).
// ============================================================
#define GS_ROWB   80
#define GS_MAT    (128 * GS_ROWB)
#define GS_STAGE  (4 * GS_MAT)
#define GS_SMEM   (2 * GS_STAGE)

__device__ __forceinline__ void hgemm_load_chunk(
    const __nv_bfloat16* __restrict__ Ah, const __nv_bfloat16* __restrict__ Al,
    const __nv_bfloat16* __restrict__ Bh, const __nv_bfloat16* __restrict__ Bl,
    int K, int bm, int bn, int k0, uint32_t sbase, int tid)
{
#pragma unroll
    for (int i = 0; i < 8; i++) {
        int task = tid + (i << 8);
        int op   = task >> 9;
        int t2   = task & 511;
        int row  = t2 >> 2;
        int g    = t2 & 3;
        const __nv_bfloat16* base;
        int grow;
        if      (op == 0) { base = Ah; grow = bm + row; }
        else if (op == 1) { base = Al; grow = bm + row; }
        else if (op == 2) { base = Bh; grow = bn + row; }
        else              { base = Bl; grow = bn + row; }
        const void* src = base + (size_t)grow * K + k0 + (g << 3);
        uint32_t dst = sbase + op * GS_MAT + row * GS_ROWB + (g << 4);
        cp16(dst, src);
    }
}

__device__ __forceinline__ void hgemm_body(
    const __nv_bfloat16* __restrict__ Ah, const __nv_bfloat16* __restrict__ Al,
    const __nv_bfloat16* __restrict__ Bh, const __nv_bfloat16* __restrict__ Bl,
    float* __restrict__ C, int K, int N, int bm, int bn, int mode)
{
    extern __shared__ __align__(128) char sm[];
    const uint32_t smb = smem_u32(sm);
    const int tid  = threadIdx.x;
    const int wid  = tid >> 5;
    const int lane = tid & 31;
    const int wm = (wid >> 2) << 6;
    const int wn = (wid & 3) << 5;

    const int rA = (lane & 7) + ((lane >> 3) & 1) * 8;
    const int cA = (lane >> 4) << 3;
    const int rB = (lane & 7) + ((lane >> 4) << 3);
    const int cB = ((lane >> 3) & 1) << 3;

    float acc[4][4][4];
#pragma unroll
    for (int mt = 0; mt < 4; mt++)
#pragma unroll
        for (int nt = 0; nt < 4; nt++)
#pragma unroll
            for (int e = 0; e < 4; e++) acc[mt][nt][e] = 0.f;

    const int NC = K >> 5;

    hgemm_load_chunk(Ah, Al, Bh, Bl, K, bm, bn, 0, smb, tid);
    cp_commit();
    hgemm_load_chunk(Ah, Al, Bh, Bl, K, bm, bn, 32, smb + GS_STAGE, tid);
    cp_commit();

    for (int c = 0; c < NC; c++) {
        const uint32_t sb = smb + (c & 1) * GS_STAGE;
        if (c + 1 < NC) cp_wait<1>(); else cp_wait<0>();
        __syncthreads();

#pragma unroll
        for (int ks = 0; ks < 2; ks++) {
            const int k0 = ks << 4;
            uint32_t ah[4][4], al[4][4], bh[2][4], bl[2][4];
#pragma unroll
            for (int mt = 0; mt < 4; mt++) {
                uint32_t ro = (uint32_t)(wm + (mt << 4) + rA) * GS_ROWB + ((k0 + cA) << 1);
                ldm_x4(ah[mt], sb + 0 * GS_MAT + ro);
                ldm_x4(al[mt], sb + 1 * GS_MAT + ro);
            }
#pragma unroll
            for (int nt2 = 0; nt2 < 2; nt2++) {
                uint32_t ro = (uint32_t)(wn + (nt2 << 4) + rB) * GS_ROWB + ((k0 + cB) << 1);
                ldm_x4(bh[nt2], sb + 2 * GS_MAT + ro);
                ldm_x4(bl[nt2], sb + 3 * GS_MAT + ro);
            }
#pragma unroll
            for (int mt = 0; mt < 4; mt++)
#pragma unroll
                for (int nt = 0; nt < 4; nt++) {
                    const uint32_t* bhp = &bh[nt >> 1][(nt & 1) << 1];
                    const uint32_t* blp = &bl[nt >> 1][(nt & 1) << 1];
                    mma_bf16(acc[mt][nt], ah[mt], bhp);
                    mma_bf16(acc[mt][nt], ah[mt], blp);
                    mma_bf16(acc[mt][nt], al[mt], bhp);
                }
        }
        __syncthreads();
        if (c + 2 < NC) {
            hgemm_load_chunk(Ah, Al, Bh, Bl, K, bm, bn, (c + 2) << 5,
                             smb + (c & 1) * GS_STAGE, tid);
        }
        cp_commit();
    }

    const int g  = lane >> 2;
    const int tg = lane & 3;
    if (mode == 0) {
#pragma unroll
        for (int mt = 0; mt < 4; mt++) {
            const int row0 = bm + wm + (mt << 4) + g;
#pragma unroll
            for (int nt = 0; nt < 4; nt++) {
                const int col = bn + wn + (nt << 3) + (tg << 1);
                *(float2*)&C[(size_t)row0 * N + col] =
                    make_float2(acc[mt][nt][0], acc[mt][nt][1]);
                *(float2*)&C[(size_t)(row0 + 8) * N + col] =
                    make_float2(acc[mt][nt][2], acc[mt][nt][3]);
            }
        }
    } else {
        // rope + 0.125 scale -> g_qf (fp16); layout (b*T+row)*1024 + col
#pragma unroll
        for (int mt = 0; mt < 4; mt++) {
            const int row0 = bm + wm + (mt << 4) + g;
            const int t0 = row0 & (T_ - 1);
            const int t1 = (row0 + 8) & (T_ - 1);
#pragma unroll
            for (int nt = 0; nt < 4; nt++) {
                const int col = bn + wn + (nt << 3) + (tg << 1);
                const int d0 = col & 63, d1 = d0 + 1;
                float q0 = acc[mt][nt][0] * 0.125f, q1 = acc[mt][nt][1] * 0.125f;
                float c0 = g_cos[t0*DH+d0], s0 = g_sin[t0*DH+d0];
                float c1 = g_cos[t0*DH+d1], s1 = g_sin[t0*DH+d1];
                ((uint32_t*)g_qf)[((size_t)row0 * CDIM + col) >> 1] =
                    pack_h2(q0*c0 - q1*s0, q1*c1 + q0*s1);
                q0 = acc[mt][nt][2] * 0.125f; q1 = acc[mt][nt][3] * 0.125f;
                c0 = g_cos[t1*DH+d0]; s0 = g_sin[t1*DH+d0];
                c1 = g_cos[t1*DH+d1]; s1 = g_sin[t1*DH+d1];
                ((uint32_t*)g_qf)[((size_t)(row0 + 8) * CDIM + col) >> 1] =
                    pack_h2(q0*c0 - q1*s0, q1*c1 + q0*s1);
            }
        }
    }
}

// unified projection launch: z=0 -> Wq (rope epi), z=1 -> K (x<4) / V (x>=4)
__global__ void __launch_bounds__(256, 1)
proj_gemm(const __nv_bfloat16* __restrict__ xh, const __nv_bfloat16* __restrict__ xl,
          const __nv_bfloat16* __restrict__ wh, const __nv_bfloat16* __restrict__ wl,
          float* __restrict__ Ck, float* __restrict__ Cv)
{
    const int bm = blockIdx.y << 7;
    if (blockIdx.z == 0) {
        hgemm_body(xh, xl, wh + WQ_OFF, wl + WQ_OFF, nullptr,
                   CDIM, CDIM, bm, blockIdx.x << 7, 1);
    } else if (blockIdx.x < 4) {
        hgemm_body(xh, xl, wh + WK_OFF, wl + WK_OFF, Ck,
                   CDIM, 512, bm, blockIdx.x << 7, 0);
    } else {
        hgemm_body(xh, xl, wh + WV_OFF, wl + WV_OFF, Cv,
                   CDIM, 512, bm, (blockIdx.x - 4) << 7, 0);
    }
}

__global__ void __launch_bounds__(256, 1)
hgemm_wc(const __nv_bfloat16* __restrict__ Ah, const __nv_bfloat16* __restrict__ Al,
         const __nv_bfloat16* __restrict__ Bh, const __nv_bfloat16* __restrict__ Bl,
         float* __restrict__ C)
{
    hgemm_body(Ah, Al, Bh, Bl, C, CDIM, CDIM, blockIdx.y << 7, blockIdx.x << 7, 0);
}

// ============================================================
// RoPE table
// ============================================================
__global__ void rope_table_kernel() {
    int t = blockIdx.x;
    int c = threadIdx.x;
    int j = c & 31;
    double inv = pow(10000.0, -(double)j / 32.0);
    float  ang = (float)t * (float)inv;
    double s, cc;
    sincos((double)ang, &s, &cc);
    g_cos[t * DH + c] = (float)cc;
    g_sin[t * DH + c] = (float)s;
}

// ============================================================
// Up-projection + RoPE for k, v -> fp16
// ============================================================
__global__ void __launch_bounds__(256)
upproj_rope_kernel(const float* __restrict__ klat, const float* __restrict__ vlat,
                   const float* __restrict__ Wku,  const float* __restrict__ Wvu)
{
    const int bt = blockIdx.x;
    const int t  = bt & (T_ - 1);
    __shared__ float skl[512], svl[512];
    __shared__ float swk[64 * 33], swv[64 * 33];
    const int tid = threadIdx.x;

    skl[tid]       = klat[(size_t)bt * 512 + tid];
    skl[tid + 256] = klat[(size_t)bt * 512 + tid + 256];
    svl[tid]       = vlat[(size_t)bt * 512 + tid];
    svl[tid + 256] = vlat[(size_t)bt * 512 + tid + 256];
    for (int i = tid; i < 64 * 32; i += 256) {
        int d = i >> 5, l = i & 31;
        swk[d * 33 + l] = Wku[i];
        swv[d * 33 + l] = Wvu[i];
    }
    __syncthreads();

#pragma unroll
    for (int p = tid; p < 512; p += 256) {
        const int h  = p >> 5, i = p & 31;
        const int d0 = i << 1, d1 = d0 + 1;
        const float* kl  = &skl[h << 5];
        const float* vl  = &svl[h << 5];
        const float* wk0 = &swk[d0 * 33];
        const float* wk1 = &swk[d1 * 33];
        const float* wv0 = &swv[d0 * 33];
        const float* wv1 = &swv[d1 * 33];
        float k0 = 0.f, k1 = 0.f, v0 = 0.f, v1 = 0.f;
#pragma unroll
        for (int l = 0; l < 32; l++) {
            float klv = kl[l], vlv = vl[l];
            k0 = fmaf(klv, wk0[l], k0);
            k1 = fmaf(klv, wk1[l], k1);
            v0 = fmaf(vlv, wv0[l], v0);
            v1 = fmaf(vlv, wv1[l], v1);
        }
        const float c0 = g_cos[t * DH + d0], s0 = g_sin[t * DH + d0];
        const float c1 = g_cos[t * DH + d1], s1 = g_sin[t * DH + d1];
        const size_t pi = (((size_t)bt * H_ + h) * DH + d0) >> 1;
        ((uint32_t*)g_kf)[pi] = pack_h2(k0 * c0 - k1 * s0, k1 * c1 + k0 * s1);
        ((uint32_t*)g_vf)[pi] = pack_h2(v0, v1);
    }
}

// ============================================================
// fp16 HMMA causal flash attention (single-precision MMA).
// CTA: 128 q rows, 8 warps x 16 rows. K-blocks of 64, double-buffered.
// ============================================================
#define AT_ROWB   144
#define AT_MAT    (64 * AT_ROWB)        // 9216 (one 64x64 fp16 tile)
#define AT_STAGE  (2 * AT_MAT)          // Kf, Vf
#define AT_QOFF   (2 * AT_STAGE)        // 36864
#define AT_QMAT   (128 * AT_ROWB)       // 18432
#define AT_SMEM   (AT_QOFF + AT_QMAT)   // 55296

__device__ __forceinline__ void attn_load_kv(int b, int h, int kb,
                                             uint32_t sbase, int tid)
{
    const int k0 = kb << 6;
#pragma unroll
    for (int i = 0; i < 4; i++) {
        int task = tid + (i << 8);     // 1024: op(2) x row(64) x granule(8)
        int op = task >> 9;
        int t2 = task & 511;
        int row = t2 >> 3, g = t2 & 7;
        const __half* base = op ? g_vf : g_kf;
        const void* src = base + ((size_t)(b * T_ + k0 + row) * H_ + h) * DH + (g << 3);
        cp16(sbase + op * AT_MAT + row * AT_ROWB + (g << 4), src);
    }
}

__global__ void __launch_bounds__(256, 1)
attn_mma_kernel()
{
    extern __shared__ __align__(128) char sm[];
    const uint32_t smb = smem_u32(sm);
    const int tid = threadIdx.x;
    const int wid = tid >> 5, lane = tid & 31;
    const int qt = gridDim.x - 1 - blockIdx.x;   // heavy blocks first
    const int h = blockIdx.y, b = blockIdx.z;
    const int q0 = qt << 7;
    const int nkb = 2 * qt + 2;
    const int g = lane >> 2, tg = lane & 3;

    // Q tile load (fp16, 128 rows)
#pragma unroll
    for (int i = 0; i < 4; i++) {
        int task = tid + (i << 8);
        int row = task >> 3, gg = task & 7;
        const void* src = g_qf + ((size_t)(b * T_ + q0 + row) * H_ + h) * DH + (gg << 3);
        cp16(smb + AT_QOFF + row * AT_ROWB + (gg << 4), src);
    }
    cp_commit();
    attn_load_kv(b, h, 0, smb, tid);
    cp_commit();
    if (nkb > 1) attn_load_kv(b, h, 1, smb + AT_STAGE, tid);
    cp_commit();

    cp_wait<2>();
    __syncthreads();

    // persistent Q fragments
    const int rA = (lane & 7) + ((lane >> 3) & 1) * 8;
    const int cA = (lane >> 4) << 3;
    uint32_t qf[4][4];
#pragma unroll
    for (int kf = 0; kf < 4; kf++) {
        uint32_t ro = (uint32_t)(wid * 16 + rA) * AT_ROWB + ((kf * 16 + cA) << 1);
        ldm_x4(qf[kf], smb + AT_QOFF + ro);
    }

    const int rB = (lane & 7) + ((lane >> 4) << 3);
    const int cB = ((lane >> 3) & 1) << 3;
    const int rV = lane & 15;
    const int cV = (lane >> 4) << 4;

    float yacc[8][4];
#pragma unroll
    for (int i = 0; i < 8; i++)
#pragma unroll
        for (int e = 0; e < 4; e++) yacc[i][e] = 0.f;
    float m0 = -1e30f, m1 = -1e30f, l0 = 0.f, l1 = 0.f;

    for (int kb = 0; kb < nkb; kb++) {
        const uint32_t sb = smb + (kb & 1) * AT_STAGE;
        if (kb + 1 < nkb) cp_wait<1>(); else cp_wait<0>();
        __syncthreads();

        // ---- S = Q K^T ----
        float s[8][4];
#pragma unroll
        for (int i = 0; i < 8; i++)
#pragma unroll
            for (int e = 0; e < 4; e++) s[i][e] = 0.f;
#pragma unroll
        for (int kf = 0; kf < 4; kf++) {
#pragma unroll
            for (int nt16 = 0; nt16 < 4; nt16++) {
                uint32_t ro = (uint32_t)(nt16 * 16 + rB) * AT_ROWB + ((kf * 16 + cB) << 1);
                uint32_t bk[4];
                ldm_x4(bk, sb + ro);
                mma_f16(s[nt16 * 2],     qf[kf], &bk[0]);
                mma_f16(s[nt16 * 2 + 1], qf[kf], &bk[2]);
            }
        }

        // ---- causal mask (diagonal blocks only) ----
        if (kb >= 2 * qt) {
            const int row0 = q0 + wid * 16 + g;
#pragma unroll
            for (int nt = 0; nt < 8; nt++) {
                const int col0 = (kb << 6) + nt * 8 + (tg << 1);
                if (col0     > row0)     s[nt][0] = -1e30f;
                if (col0 + 1 > row0)     s[nt][1] = -1e30f;
                if (col0     > row0 + 8) s[nt][2] = -1e30f;
                if (col0 + 1 > row0 + 8) s[nt][3] = -1e30f;
            }
        }

        // ---- online softmax (fp32) ----
        float mx0 = -1e30f, mx1 = -1e30f;
#pragma unroll
        for (int nt = 0; nt < 8; nt++) {
            mx0 = fmaxf(mx0, fmaxf(s[nt][0], s[nt][1]));
            mx1 = fmaxf(mx1, fmaxf(s[nt][2], s[nt][3]));
        }
        mx0 = fmaxf(mx0, __shfl_xor_sync(0xffffffffu, mx0, 1));
        mx0 = fmaxf(mx0, __shfl_xor_sync(0xffffffffu, mx0, 2));
        mx1 = fmaxf(mx1, __shfl_xor_sync(0xffffffffu, mx1, 1));
        mx1 = fmaxf(mx1, __shfl_xor_sync(0xffffffffu, mx1, 2));
        const float mn0 = fmaxf(m0, mx0), mn1 = fmaxf(m1, mx1);
        const float a0 = __expf(m0 - mn0), a1 = __expf(m1 - mn1);
        m0 = mn0; m1 = mn1;
        float r0 = 0.f, r1 = 0.f;
#pragma unroll
        for (int nt = 0; nt < 8; nt++) {
            s[nt][0] = __expf(s[nt][0] - mn0);
            s[nt][1] = __expf(s[nt][1] - mn0);
            s[nt][2] = __expf(s[nt][2] - mn1);
            s[nt][3] = __expf(s[nt][3] - mn1);
            r0 += s[nt][0] + s[nt][1];
            r1 += s[nt][2] + s[nt][3];
        }
        r0 += __shfl_xor_sync(0xffffffffu, r0, 1);
        r0 += __shfl_xor_sync(0xffffffffu, r0, 2);
        r1 += __shfl_xor_sync(0xffffffffu, r1, 1);
        r1 += __shfl_xor_sync(0xffffffffu, r1, 2);
        l0 = l0 * a0 + r0;
        l1 = l1 * a1 + r1;
#pragma unroll
        for (int i = 0; i < 8; i++) {
            yacc[i][0] *= a0; yacc[i][1] *= a0;
            yacc[i][2] *= a1; yacc[i][3] *= a1;
        }

        // ---- O += P V (fp16 P) ----
#pragma unroll
        for (int kf = 0; kf < 4; kf++) {
            uint32_t ph[4];
            ph[0] = pack_h2(s[2*kf][0],   s[2*kf][1]);
            ph[1] = pack_h2(s[2*kf][2],   s[2*kf][3]);
            ph[2] = pack_h2(s[2*kf+1][0], s[2*kf+1][1]);
            ph[3] = pack_h2(s[2*kf+1][2], s[2*kf+1][3]);
#pragma unroll
            for (int dt = 0; dt < 4; dt++) {
                uint32_t vh[4];
                uint32_t ro = (uint32_t)(kf * 16 + rV) * AT_ROWB + dt * 32 + cV;
                ldm_x4_t(vh, sb + AT_MAT + ro);
                mma_f16(yacc[dt * 2],     ph, &vh[0]);
                mma_f16(yacc[dt * 2 + 1], ph, &vh[2]);
            }
        }

        __syncthreads();
        if (kb + 2 < nkb)
            attn_load_kv(b, h, kb + 2, smb + (kb & 1) * AT_STAGE, tid);
        cp_commit();
    }

    // ---- epilogue: y/l, bf16 hi/lo for Wc GEMM ----
    const float il0 = 1.f / l0, il1 = 1.f / l1;
    const int row0 = q0 + wid * 16 + g;
#pragma unroll
    for (int dt8 = 0; dt8 < 8; dt8++) {
        const int col = h * 64 + dt8 * 8 + (tg << 1);
        uint32_t hw, lw;
        split2(yacc[dt8][0] * il0, yacc[dt8][1] * il0, hw, lw);
        size_t o0 = ((size_t)(b * T_ + row0) * CDIM + col) >> 1;
        ((uint32_t*)g_yh)[o0] = hw; ((uint32_t*)g_yl)[o0] = lw;
        split2(yacc[dt8][2] * il1, yacc[dt8][3] * il1, hw, lw);
        size_t o1 = ((size_t)(b * T_ + row0 + 8) * CDIM + col) >> 1;
        ((uint32_t*)g_yh)[o1] = hw; ((uint32_t*)g_yl)[o1] = lw;
    }
}

// ============================================================
// launch
// ============================================================
extern "C" void kernel_launch(void* const* d_in, const int* in_sizes, int n_in,
                              void* d_out, int out_size)
{
    const float* x   = (const float*)d_in[0];
    const float* Wq  = (const float*)d_in[1];
    const float* Wk  = (const float*)d_in[2];
    const float* Wv  = (const float*)d_in[3];
    const float* Wku = (const float*)d_in[4];
    const float* Wvu = (const float*)d_in[5];
    const float* Wc  = (const float*)d_in[6];

    float* out      = (float*)d_out;
    float* y_out    = out;
    float* klat_out = out + Y_ELEMS;
    float* vlat_out = out + Y_ELEMS + KL_ELEMS;

    __nv_bfloat16 *xh, *xl, *yh, *yl, *wh, *wl;
    cudaGetSymbolAddress((void**)&xh, g_xh);
    cudaGetSymbolAddress((void**)&xl, g_xl);
    cudaGetSymbolAddress((void**)&yh, g_yh);
    cudaGetSymbolAddress((void**)&yl, g_yl);
    cudaGetSymbolAddress((void**)&wh, g_wh);
    cudaGetSymbolAddress((void**)&wl, g_wl);

    cudaFuncSetAttribute(attn_mma_kernel, cudaFuncAttributeMaxDynamicSharedMemorySize, AT_SMEM);
    cudaFuncSetAttribute(proj_gemm, cudaFuncAttributeMaxDynamicSharedMemorySize, GS_SMEM);
    cudaFuncSetAttribute(hgemm_wc, cudaFuncAttributeMaxDynamicSharedMemorySize, GS_SMEM);

    // 1. rope tables
    rope_table_kernel<<<T_, 64>>>();

    // 2. splits (x: 1M granules; weights: 768K granules)
    split_x_kernel<<<4096, 256>>>(x);
    split_w_kernel<<<3072, 256>>>(Wq, Wk, Wv, Wc);

    // 3. unified projection GEMM: Wq(rope->fp16 q) + k_lat + v_lat
    dim3 gp(8, (B_ * T_) / 128, 2);
    proj_gemm<<<gp, 256, GS_SMEM>>>(xh, xl, wh, wl, klat_out, vlat_out);

    // 4. up-project + RoPE -> fp16 k, v
    upproj_rope_kernel<<<B_ * T_, 256>>>(klat_out, vlat_out, Wku, Wvu);

    // 5. fp16 HMMA causal flash attention -> g_yh/g_yl
    dim3 ga(T_ / 128, H_, B_);
    attn_mma_kernel<<<ga, 256, AT_SMEM>>>();

    // 6. y = attn @ Wc^T (split-bf16)
    dim3 gc(8, (B_ * T_) / 128);
    hgemm_wc<<<gc, 256, GS_SMEM>>>(yh, yl, wh + WC_OFF, wl + WC_OFF, y_out);
}

// round 6
// speedup vs baseline: 3.3502x; 1.0416x over previous
#include <cuda_runtime.h>
#include <cuda_bf16.h>
#include <cuda_fp16.h>
#include <math.h>
#include <stdint.h>

#define B_   2
#define T_   2048
#define H_   16
#define DH   64
#define DL   32
#define CDIM 1024

#define Y_ELEMS  ((size_t)B_*T_*CDIM)
#define KL_ELEMS ((size_t)B_*T_*H_*DL)

// ---- scratch ----
__device__ float g_cos[T_*DH];
__device__ float g_sin[T_*DH];

__device__ __nv_bfloat16 g_xh[(size_t)B_*T_*CDIM];
__device__ __nv_bfloat16 g_xl[(size_t)B_*T_*CDIM];
__device__ __nv_bfloat16 g_yh[(size_t)B_*T_*CDIM];
__device__ __nv_bfloat16 g_yl[(size_t)B_*T_*CDIM];
__device__ __half g_qf[(size_t)B_*T_*H_*DH];
__device__ __half g_kf[(size_t)B_*T_*H_*DH];
__device__ __half g_vf[(size_t)B_*T_*H_*DH];
__device__ __nv_bfloat16 g_wh[3u*1024*1024];
__device__ __nv_bfloat16 g_wl[3u*1024*1024];
#define WQ_OFF 0u
#define WK_OFF (1024u*1024u)
#define WV_OFF (1536u*1024u)
#define WC_OFF (2048u*1024u)

// ============================================================
// PTX helpers
// ============================================================
__device__ __forceinline__ uint32_t smem_u32(const void* p) {
    uint32_t a;
    asm("{ .reg .u64 t; cvta.to.shared.u64 t, %1; cvt.u32.u64 %0, t; }"
        : "=r"(a) : "l"(p));
    return a;
}
__device__ __forceinline__ void cp16(uint32_t dst, const void* src) {
    asm volatile("cp.async.cg.shared.global [%0], [%1], 16;\n"
                 :: "r"(dst), "l"(src));
}
__device__ __forceinline__ void cp_commit() {
    asm volatile("cp.async.commit_group;\n" ::: "memory");
}
template<int N> __device__ __forceinline__ void cp_wait() {
    asm volatile("cp.async.wait_group %0;\n" :: "n"(N) : "memory");
}
__device__ __forceinline__ void ldm_x4(uint32_t* r, uint32_t addr) {
    asm volatile("ldmatrix.sync.aligned.m8n8.x4.shared.b16 {%0,%1,%2,%3}, [%4];"
        : "=r"(r[0]), "=r"(r[1]), "=r"(r[2]), "=r"(r[3]) : "r"(addr));
}
__device__ __forceinline__ void ldm_x4_t(uint32_t* r, uint32_t addr) {
    asm volatile("ldmatrix.sync.aligned.m8n8.x4.trans.shared.b16 {%0,%1,%2,%3}, [%4];"
        : "=r"(r[0]), "=r"(r[1]), "=r"(r[2]), "=r"(r[3]) : "r"(addr));
}
__device__ __forceinline__ void mma_bf16(float* c, const uint32_t* a, const uint32_t* b) {
    asm volatile("mma.sync.aligned.m16n8k16.row.col.f32.bf16.bf16.f32 "
        "{%0,%1,%2,%3}, {%4,%5,%6,%7}, {%8,%9}, {%0,%1,%2,%3};\n"
        : "+f"(c[0]), "+f"(c[1]), "+f"(c[2]), "+f"(c[3])
        : "r"(a[0]), "r"(a[1]), "r"(a[2]), "r"(a[3]), "r"(b[0]), "r"(b[1]));
}
__device__ __forceinline__ void mma_f16(float* c, const uint32_t* a, const uint32_t* b) {
    asm volatile("mma.sync.aligned.m16n8k16.row.col.f32.f16.f16.f32 "
        "{%0,%1,%2,%3}, {%4,%5,%6,%7}, {%8,%9}, {%0,%1,%2,%3};\n"
        : "+f"(c[0]), "+f"(c[1]), "+f"(c[2]), "+f"(c[3])
        : "r"(a[0]), "r"(a[1]), "r"(a[2]), "r"(a[3]), "r"(b[0]), "r"(b[1]));
}
__device__ __forceinline__ void split2(float a, float b, uint32_t& h, uint32_t& l) {
    __nv_bfloat16 ha = __float2bfloat16(a), hb = __float2bfloat16(b);
    __nv_bfloat16 la = __float2bfloat16(a - __bfloat162float(ha));
    __nv_bfloat16 lb = __float2bfloat16(b - __bfloat162float(hb));
    h = (uint32_t)__bfloat16_as_ushort(ha) | ((uint32_t)__bfloat16_as_ushort(hb) << 16);
    l = (uint32_t)__bfloat16_as_ushort(la) | ((uint32_t)__bfloat16_as_ushort(lb) << 16);
}
__device__ __forceinline__ uint32_t pack_h2(float a, float b) {
    __half2 h = __floats2half2_rn(a, b);
    return *(uint32_t*)&h;
}

// ============================================================
// split kernels (fp32 -> bf16 hi/lo)
// ============================================================
__device__ __forceinline__ void split_store4(const float4 v,
                                             uint32_t* hi, uint32_t* lo, size_t i2)
{
    uint32_t h0, l0, h1, l1;
    split2(v.x, v.y, h0, l0);
    split2(v.z, v.w, h1, l1);
    hi[i2]   = h0; hi[i2+1] = h1;
    lo[i2]   = l0; lo[i2+1] = l1;
}

__global__ void __launch_bounds__(256)
split_x_kernel(const float* __restrict__ in)
{
    int i = blockIdx.x * blockDim.x + threadIdx.x;
    float4 v = ((const float4*)in)[i];
    split_store4(v, (uint32_t*)g_xh, (uint32_t*)g_xl, 2 * (size_t)i);
}

__global__ void __launch_bounds__(256)
split_w_kernel(const float* __restrict__ Wq, const float* __restrict__ Wk,
               const float* __restrict__ Wv, const float* __restrict__ Wc)
{
    int i = blockIdx.x * blockDim.x + threadIdx.x;
    const float* src; int off;
    if      (i < 262144) { src = Wq; off = i; }
    else if (i < 393216) { src = Wk; off = i - 262144; }
    else if (i < 524288) { src = Wv; off = i - 393216; }
    else                 { src = Wc; off = i - 524288; }
    float4 v = ((const float4*)src)[off];
    split_store4(v, (uint32_t*)g_wh, (uint32_t*)g_wl, 2 * (size_t)i);
}

// ============================================================
// HMMA GEMM: 3-stage single-sync pipeline, pass-reordered MMAs.
// ============================================================
#define GS_ROWB   80
#define GS_MAT    (128 * GS_ROWB)
#define GS_STAGE  (4 * GS_MAT)          // 40960
#define GS_SMEM   (3 * GS_STAGE)        // 122880

__device__ __forceinline__ void hgemm_load_chunk(
    const __nv_bfloat16* __restrict__ Ah, const __nv_bfloat16* __restrict__ Al,
    const __nv_bfloat16* __restrict__ Bh, const __nv_bfloat16* __restrict__ Bl,
    int K, int bm, int bn, int k0, uint32_t sbase, int tid)
{
#pragma unroll
    for (int i = 0; i < 8; i++) {
        int task = tid + (i << 8);
        int op   = task >> 9;
        int t2   = task & 511;
        int row  = t2 >> 2;
        int g    = t2 & 3;
        const __nv_bfloat16* base;
        int grow;
        if      (op == 0) { base = Ah; grow = bm + row; }
        else if (op == 1) { base = Al; grow = bm + row; }
        else if (op == 2) { base = Bh; grow = bn + row; }
        else              { base = Bl; grow = bn + row; }
        const void* src = base + (size_t)grow * K + k0 + (g << 3);
        uint32_t dst = sbase + op * GS_MAT + row * GS_ROWB + (g << 4);
        cp16(dst, src);
    }
}

__device__ __forceinline__ void hgemm_body(
    const __nv_bfloat16* __restrict__ Ah, const __nv_bfloat16* __restrict__ Al,
    const __nv_bfloat16* __restrict__ Bh, const __nv_bfloat16* __restrict__ Bl,
    float* __restrict__ C, int K, int N, int bm, int bn, int mode)
{
    extern __shared__ __align__(128) char sm[];
    const uint32_t smb = smem_u32(sm);
    const int tid  = threadIdx.x;
    const int wid  = tid >> 5;
    const int lane = tid & 31;
    const int wm = (wid >> 2) << 6;
    const int wn = (wid & 3) << 5;

    const int rA = (lane & 7) + ((lane >> 3) & 1) * 8;
    const int cA = (lane >> 4) << 3;
    const int rB = (lane & 7) + ((lane >> 4) << 3);
    const int cB = ((lane >> 3) & 1) << 3;

    float acc[4][4][4];
#pragma unroll
    for (int mt = 0; mt < 4; mt++)
#pragma unroll
        for (int nt = 0; nt < 4; nt++)
#pragma unroll
            for (int e = 0; e < 4; e++) acc[mt][nt][e] = 0.f;

    const int NC = K >> 5;

    // prefetch stages 0,1 (buffers 0,1); 3rd buffer filled in-loop
    hgemm_load_chunk(Ah, Al, Bh, Bl, K, bm, bn, 0, smb, tid);
    cp_commit();
    hgemm_load_chunk(Ah, Al, Bh, Bl, K, bm, bn, 32, smb + GS_STAGE, tid);
    cp_commit();

    int bc = 0, bp = 2;    // compute buffer, prefetch buffer
    for (int c = 0; c < NC; c++) {
        cp_wait<1>();              // stage c arrived (c+1 may be in flight)
        __syncthreads();           // everyone done reading buffer bp (stage c-1 use)
        if (c + 2 < NC)
            hgemm_load_chunk(Ah, Al, Bh, Bl, K, bm, bn, (c + 2) << 5,
                             smb + bp * GS_STAGE, tid);
        cp_commit();
        const uint32_t sb = smb + bc * GS_STAGE;
        bc = (bc == 2) ? 0 : bc + 1;
        bp = (bp == 2) ? 0 : bp + 1;

#pragma unroll
        for (int ks = 0; ks < 2; ks++) {
            const int k0 = ks << 4;
            uint32_t ah[4][4], al[4][4], bh[2][4], bl[2][4];
#pragma unroll
            for (int mt = 0; mt < 4; mt++) {
                uint32_t ro = (uint32_t)(wm + (mt << 4) + rA) * GS_ROWB + ((k0 + cA) << 1);
                ldm_x4(ah[mt], sb + 0 * GS_MAT + ro);
                ldm_x4(al[mt], sb + 1 * GS_MAT + ro);
            }
#pragma unroll
            for (int nt2 = 0; nt2 < 2; nt2++) {
                uint32_t ro = (uint32_t)(wn + (nt2 << 4) + rB) * GS_ROWB + ((k0 + cB) << 1);
                ldm_x4(bh[nt2], sb + 2 * GS_MAT + ro);
                ldm_x4(bl[nt2], sb + 3 * GS_MAT + ro);
            }
            // pass-reordered: 16 independent accumulators between reuses
#pragma unroll
            for (int mt = 0; mt < 4; mt++)
#pragma unroll
                for (int nt = 0; nt < 4; nt++)
                    mma_bf16(acc[mt][nt], ah[mt], &bh[nt >> 1][(nt & 1) << 1]);
#pragma unroll
            for (int mt = 0; mt < 4; mt++)
#pragma unroll
                for (int nt = 0; nt < 4; nt++)
                    mma_bf16(acc[mt][nt], ah[mt], &bl[nt >> 1][(nt & 1) << 1]);
#pragma unroll
            for (int mt = 0; mt < 4; mt++)
#pragma unroll
                for (int nt = 0; nt < 4; nt++)
                    mma_bf16(acc[mt][nt], al[mt], &bh[nt >> 1][(nt & 1) << 1]);
        }
    }

    const int g  = lane >> 2;
    const int tg = lane & 3;
    if (mode == 0) {
#pragma unroll
        for (int mt = 0; mt < 4; mt++) {
            const int row0 = bm + wm + (mt << 4) + g;
#pragma unroll
            for (int nt = 0; nt < 4; nt++) {
                const int col = bn + wn + (nt << 3) + (tg << 1);
                *(float2*)&C[(size_t)row0 * N + col] =
                    make_float2(acc[mt][nt][0], acc[mt][nt][1]);
                *(float2*)&C[(size_t)(row0 + 8) * N + col] =
                    make_float2(acc[mt][nt][2], acc[mt][nt][3]);
            }
        }
    } else {
#pragma unroll
        for (int mt = 0; mt < 4; mt++) {
            const int row0 = bm + wm + (mt << 4) + g;
            const int t0 = row0 & (T_ - 1);
            const int t1 = (row0 + 8) & (T_ - 1);
#pragma unroll
            for (int nt = 0; nt < 4; nt++) {
                const int col = bn + wn + (nt << 3) + (tg << 1);
                const int d0 = col & 63, d1 = d0 + 1;
                float q0 = acc[mt][nt][0] * 0.125f, q1 = acc[mt][nt][1] * 0.125f;
                float c0 = g_cos[t0*DH+d0], s0 = g_sin[t0*DH+d0];
                float c1 = g_cos[t0*DH+d1], s1 = g_sin[t0*DH+d1];
                ((uint32_t*)g_qf)[((size_t)row0 * CDIM + col) >> 1] =
                    pack_h2(q0*c0 - q1*s0, q1*c1 + q0*s1);
                q0 = acc[mt][nt][2] * 0.125f; q1 = acc[mt][nt][3] * 0.125f;
                c0 = g_cos[t1*DH+d0]; s0 = g_sin[t1*DH+d0];
                c1 = g_cos[t1*DH+d1]; s1 = g_sin[t1*DH+d1];
                ((uint32_t*)g_qf)[((size_t)(row0 + 8) * CDIM + col) >> 1] =
                    pack_h2(q0*c0 - q1*s0, q1*c1 + q0*s1);
            }
        }
    }
}

__global__ void __launch_bounds__(256, 1)
proj_gemm(const __nv_bfloat16* __restrict__ xh, const __nv_bfloat16* __restrict__ xl,
          const __nv_bfloat16* __restrict__ wh, const __nv_bfloat16* __restrict__ wl,
          float* __restrict__ Ck, float* __restrict__ Cv)
{
    const int bm = blockIdx.y << 7;
    if (blockIdx.z == 0) {
        hgemm_body(xh, xl, wh + WQ_OFF, wl + WQ_OFF, nullptr,
                   CDIM, CDIM, bm, blockIdx.x << 7, 1);
    } else if (blockIdx.x < 4) {
        hgemm_body(xh, xl, wh + WK_OFF, wl + WK_OFF, Ck,
                   CDIM, 512, bm, blockIdx.x << 7, 0);
    } else {
        hgemm_body(xh, xl, wh + WV_OFF, wl + WV_OFF, Cv,
                   CDIM, 512, bm, (blockIdx.x - 4) << 7, 0);
    }
}

__global__ void __launch_bounds__(256, 1)
hgemm_wc(const __nv_bfloat16* __restrict__ Ah, const __nv_bfloat16* __restrict__ Al,
         const __nv_bfloat16* __restrict__ Bh, const __nv_bfloat16* __restrict__ Bl,
         float* __restrict__ C)
{
    hgemm_body(Ah, Al, Bh, Bl, C, CDIM, CDIM, blockIdx.y << 7, blockIdx.x << 7, 0);
}

// ============================================================
// RoPE table
// ============================================================
__global__ void rope_table_kernel() {
    int t = blockIdx.x;
    int c = threadIdx.x;
    int j = c & 31;
    double inv = pow(10000.0, -(double)j / 32.0);
    float  ang = (float)t * (float)inv;
    double s, cc;
    sincos((double)ang, &s, &cc);
    g_cos[t * DH + c] = (float)cc;
    g_sin[t * DH + c] = (float)s;
}

// ============================================================
// Up-projection + RoPE for k, v -> fp16. 4 tokens per CTA.
// ============================================================
__global__ void __launch_bounds__(256)
upproj_rope_kernel(const float* __restrict__ klat, const float* __restrict__ vlat,
                   const float* __restrict__ Wku,  const float* __restrict__ Wvu)
{
    const int bt0 = blockIdx.x << 2;
    __shared__ float skl[2048], svl[2048];
    __shared__ float swk[64 * 33], swv[64 * 33];
    const int tid = threadIdx.x;

    for (int u = tid; u < 512; u += 256) {
        ((float4*)skl)[u] = ((const float4*)(klat + (size_t)bt0 * 512))[u];
        ((float4*)svl)[u] = ((const float4*)(vlat + (size_t)bt0 * 512))[u];
    }
    for (int i = tid; i < 64 * 32; i += 256) {
        int d = i >> 5, l = i & 31;
        swk[d * 33 + l] = Wku[i];
        swv[d * 33 + l] = Wvu[i];
    }
    __syncthreads();

#pragma unroll
    for (int u = 0; u < 8; u++) {
        const int unit = tid + (u << 8);        // 0..2047
        const int tok = unit >> 9;
        const int p   = unit & 511;
        const int h  = p >> 5, i = p & 31;
        const int d0 = i << 1, d1 = d0 + 1;
        const int bt = bt0 + tok;
        const int t  = bt & (T_ - 1);
        const float* kl  = &skl[(tok << 9) + (h << 5)];
        const float* vl  = &svl[(tok << 9) + (h << 5)];
        const float* wk0 = &swk[d0 * 33];
        const float* wk1 = &swk[d1 * 33];
        const float* wv0 = &swv[d0 * 33];
        const float* wv1 = &swv[d1 * 33];
        float k0 = 0.f, k1 = 0.f, v0 = 0.f, v1 = 0.f;
#pragma unroll
        for (int l = 0; l < 32; l++) {
            float klv = kl[l], vlv = vl[l];
            k0 = fmaf(klv, wk0[l], k0);
            k1 = fmaf(klv, wk1[l], k1);
            v0 = fmaf(vlv, wv0[l], v0);
            v1 = fmaf(vlv, wv1[l], v1);
        }
        const float c0 = g_cos[t * DH + d0], s0 = g_sin[t * DH + d0];
        const float c1 = g_cos[t * DH + d1], s1 = g_sin[t * DH + d1];
        const size_t pi = (((size_t)bt * H_ + h) * DH + d0) >> 1;
        ((uint32_t*)g_kf)[pi] = pack_h2(k0 * c0 - k1 * s0, k1 * c1 + k0 * s1);
        ((uint32_t*)g_vf)[pi] = pack_h2(v0, v1);
    }
}

// ============================================================
// fp16 HMMA causal flash attention, 3-buffer single-sync KV
// pipeline, 2 CTAs/SM.
// ============================================================
#define AT_ROWB   144
#define AT_MAT    (64 * AT_ROWB)        // 9216
#define AT_STAGE  (2 * AT_MAT)          // 18432 (Kf, Vf)
#define AT_QOFF   (3 * AT_STAGE)        // 55296
#define AT_QMAT   (128 * AT_ROWB)       // 18432
#define AT_SMEM   (AT_QOFF + AT_QMAT)   // 73728

__device__ __forceinline__ void attn_load_kv(int b, int h, int kb,
                                             uint32_t sbase, int tid)
{
    const int k0 = kb << 6;
#pragma unroll
    for (int i = 0; i < 4; i++) {
        int task = tid + (i << 8);
        int op = task >> 9;
        int t2 = task & 511;
        int row = t2 >> 3, g = t2 & 7;
        const __half* base = op ? g_vf : g_kf;
        const void* src = base + ((size_t)(b * T_ + k0 + row) * H_ + h) * DH + (g << 3);
        cp16(sbase + op * AT_MAT + row * AT_ROWB + (g << 4), src);
    }
}

__global__ void __launch_bounds__(256, 2)
attn_mma_kernel()
{
    extern __shared__ __align__(128) char sm[];
    const uint32_t smb = smem_u32(sm);
    const int tid = threadIdx.x;
    const int wid = tid >> 5, lane = tid & 31;
    const int qt = gridDim.x - 1 - blockIdx.x;
    const int h = blockIdx.y, b = blockIdx.z;
    const int q0 = qt << 7;
    const int nkb = 2 * qt + 2;
    const int g = lane >> 2, tg = lane & 3;

    // Q tile (own group), then KV stages 0,1
#pragma unroll
    for (int i = 0; i < 4; i++) {
        int task = tid + (i << 8);
        int row = task >> 3, gg = task & 7;
        const void* src = g_qf + ((size_t)(b * T_ + q0 + row) * H_ + h) * DH + (gg << 3);
        cp16(smb + AT_QOFF + row * AT_ROWB + (gg << 4), src);
    }
    cp_commit();
    attn_load_kv(b, h, 0, smb, tid);
    cp_commit();
    attn_load_kv(b, h, 1, smb + AT_STAGE, tid);
    cp_commit();

    // Q fragments (persistent)
    cp_wait<2>();
    __syncthreads();
    const int rA = (lane & 7) + ((lane >> 3) & 1) * 8;
    const int cA = (lane >> 4) << 3;
    uint32_t qf[4][4];
#pragma unroll
    for (int kf = 0; kf < 4; kf++) {
        uint32_t ro = (uint32_t)(wid * 16 + rA) * AT_ROWB + ((kf * 16 + cA) << 1);
        ldm_x4(qf[kf], smb + AT_QOFF + ro);
    }

    const int rB = (lane & 7) + ((lane >> 4) << 3);
    const int cB = ((lane >> 3) & 1) << 3;
    const int rV = lane & 15;
    const int cV = (lane >> 4) << 4;

    float yacc[8][4];
#pragma unroll
    for (int i = 0; i < 8; i++)
#pragma unroll
        for (int e = 0; e < 4; e++) yacc[i][e] = 0.f;
    float m0 = -1e30f, m1 = -1e30f, l0 = 0.f, l1 = 0.f;

    int bc = 0, bp = 2;
    for (int kb = 0; kb < nkb; kb++) {
        cp_wait<1>();
        __syncthreads();
        if (kb + 2 < nkb)
            attn_load_kv(b, h, kb + 2, smb + bp * AT_STAGE, tid);
        cp_commit();
        const uint32_t sb = smb + bc * AT_STAGE;
        bc = (bc == 2) ? 0 : bc + 1;
        bp = (bp == 2) ? 0 : bp + 1;

        // ---- S = Q K^T ----
        float s[8][4];
#pragma unroll
        for (int i = 0; i < 8; i++)
#pragma unroll
            for (int e = 0; e < 4; e++) s[i][e] = 0.f;
#pragma unroll
        for (int kf = 0; kf < 4; kf++) {
#pragma unroll
            for (int nt16 = 0; nt16 < 4; nt16++) {
                uint32_t ro = (uint32_t)(nt16 * 16 + rB) * AT_ROWB + ((kf * 16 + cB) << 1);
                uint32_t bk[4];
                ldm_x4(bk, sb + ro);
                mma_f16(s[nt16 * 2],     qf[kf], &bk[0]);
                mma_f16(s[nt16 * 2 + 1], qf[kf], &bk[2]);
            }
        }

        // ---- causal mask (diagonal blocks only) ----
        if (kb >= 2 * qt) {
            const int row0 = q0 + wid * 16 + g;
#pragma unroll
            for (int nt = 0; nt < 8; nt++) {
                const int col0 = (kb << 6) + nt * 8 + (tg << 1);
                if (col0     > row0)     s[nt][0] = -1e30f;
                if (col0 + 1 > row0)     s[nt][1] = -1e30f;
                if (col0     > row0 + 8) s[nt][2] = -1e30f;
                if (col0 + 1 > row0 + 8) s[nt][3] = -1e30f;
            }
        }

        // ---- online softmax (fp32) ----
        float mx0 = -1e30f, mx1 = -1e30f;
#pragma unroll
        for (int nt = 0; nt < 8; nt++) {
            mx0 = fmaxf(mx0, fmaxf(s[nt][0], s[nt][1]));
            mx1 = fmaxf(mx1, fmaxf(s[nt][2], s[nt][3]));
        }
        mx0 = fmaxf(mx0, __shfl_xor_sync(0xffffffffu, mx0, 1));
        mx0 = fmaxf(mx0, __shfl_xor_sync(0xffffffffu, mx0, 2));
        mx1 = fmaxf(mx1, __shfl_xor_sync(0xffffffffu, mx1, 1));
        mx1 = fmaxf(mx1, __shfl_xor_sync(0xffffffffu, mx1, 2));
        const float mn0 = fmaxf(m0, mx0), mn1 = fmaxf(m1, mx1);
        const float a0 = __expf(m0 - mn0), a1 = __expf(m1 - mn1);
        m0 = mn0; m1 = mn1;
        float r0 = 0.f, r1 = 0.f;
#pragma unroll
        for (int nt = 0; nt < 8; nt++) {
            s[nt][0] = __expf(s[nt][0] - mn0);
            s[nt][1] = __expf(s[nt][1] - mn0);
            s[nt][2] = __expf(s[nt][2] - mn1);
            s[nt][3] = __expf(s[nt][3] - mn1);
            r0 += s[nt][0] + s[nt][1];
            r1 += s[nt][2] + s[nt][3];
        }
        r0 += __shfl_xor_sync(0xffffffffu, r0, 1);
        r0 += __shfl_xor_sync(0xffffffffu, r0, 2);
        r1 += __shfl_xor_sync(0xffffffffu, r1, 1);
        r1 += __shfl_xor_sync(0xffffffffu, r1, 2);
        l0 = l0 * a0 + r0;
        l1 = l1 * a1 + r1;
#pragma unroll
        for (int i = 0; i < 8; i++) {
            yacc[i][0] *= a0; yacc[i][1] *= a0;
            yacc[i][2] *= a1; yacc[i][3] *= a1;
        }

        // ---- O += P V ----
#pragma unroll
        for (int kf = 0; kf < 4; kf++) {
            uint32_t ph[4];
            ph[0] = pack_h2(s[2*kf][0],   s[2*kf][1]);
            ph[1] = pack_h2(s[2*kf][2],   s[2*kf][3]);
            ph[2] = pack_h2(s[2*kf+1][0], s[2*kf+1][1]);
            ph[3] = pack_h2(s[2*kf+1][2], s[2*kf+1][3]);
#pragma unroll
            for (int dt = 0; dt < 4; dt++) {
                uint32_t vh[4];
                uint32_t ro = (uint32_t)(kf * 16 + rV) * AT_ROWB + dt * 32 + cV;
                ldm_x4_t(vh, sb + AT_MAT + ro);
                mma_f16(yacc[dt * 2],     ph, &vh[0]);
                mma_f16(yacc[dt * 2 + 1], ph, &vh[2]);
            }
        }
    }

    // ---- epilogue ----
    const float il0 = 1.f / l0, il1 = 1.f / l1;
    const int row0 = q0 + wid * 16 + g;
#pragma unroll
    for (int dt8 = 0; dt8 < 8; dt8++) {
        const int col = h * 64 + dt8 * 8 + (tg << 1);
        uint32_t hw, lw;
        split2(yacc[dt8][0] * il0, yacc[dt8][1] * il0, hw, lw);
        size_t o0 = ((size_t)(b * T_ + row0) * CDIM + col) >> 1;
        ((uint32_t*)g_yh)[o0] = hw; ((uint32_t*)g_yl)[o0] = lw;
        split2(yacc[dt8][2] * il1, yacc[dt8][3] * il1, hw, lw);
        size_t o1 = ((size_t)(b * T_ + row0 + 8) * CDIM + col) >> 1;
        ((uint32_t*)g_yh)[o1] = hw; ((uint32_t*)g_yl)[o1] = lw;
    }
}

// ============================================================
// launch
// ============================================================
extern "C" void kernel_launch(void* const* d_in, const int* in_sizes, int n_in,
                              void* d_out, int out_size)
{
    const float* x   = (const float*)d_in[0];
    const float* Wq  = (const float*)d_in[1];
    const float* Wk  = (const float*)d_in[2];
    const float* Wv  = (const float*)d_in[3];
    const float* Wku = (const float*)d_in[4];
    const float* Wvu = (const float*)d_in[5];
    const float* Wc  = (const float*)d_in[6];

    float* out      = (float*)d_out;
    float* y_out    = out;
    float* klat_out = out + Y_ELEMS;
    float* vlat_out = out + Y_ELEMS + KL_ELEMS;

    __nv_bfloat16 *xh, *xl, *yh, *yl, *wh, *wl;
    cudaGetSymbolAddress((void**)&xh, g_xh);
    cudaGetSymbolAddress((void**)&xl, g_xl);
    cudaGetSymbolAddress((void**)&yh, g_yh);
    cudaGetSymbolAddress((void**)&yl, g_yl);
    cudaGetSymbolAddress((void**)&wh, g_wh);
    cudaGetSymbolAddress((void**)&wl, g_wl);

    cudaFuncSetAttribute(attn_mma_kernel, cudaFuncAttributeMaxDynamicSharedMemorySize, AT_SMEM);
    cudaFuncSetAttribute(proj_gemm, cudaFuncAttributeMaxDynamicSharedMemorySize, GS_SMEM);
    cudaFuncSetAttribute(hgemm_wc, cudaFuncAttributeMaxDynamicSharedMemorySize, GS_SMEM);

    rope_table_kernel<<<T_, 64>>>();
    split_x_kernel<<<4096, 256>>>(x);
    split_w_kernel<<<3072, 256>>>(Wq, Wk, Wv, Wc);

    dim3 gp(8, (B_ * T_) / 128, 2);
    proj_gemm<<<gp, 256, GS_SMEM>>>(xh, xl, wh, wl, klat_out, vlat_out);

    upproj_rope_kernel<<<B_ * T_ / 4, 256>>>(klat_out, vlat_out, Wku, Wvu);

    dim3 ga(T_ / 128, H_, B_);
    attn_mma_kernel<<<ga, 256, AT_SMEM>>>();

    dim3 gc(8, (B_ * T_) / 128);
    hgemm_wc<<<gc, 256, GS_SMEM>>>(yh, yl, wh + WC_OFF, wl + WC_OFF, y_out);
}

// round 7
// speedup vs baseline: 3.5931x; 1.0725x over previous
#include <cuda_runtime.h>
#include <cuda_bf16.h>
#include <cuda_fp16.h>
#include <math.h>
#include <stdint.h>

#define B_   2
#define T_   2048
#define H_   16
#define DH   64
#define DL   32
#define CDIM 1024

#define Y_ELEMS  ((size_t)B_*T_*CDIM)
#define KL_ELEMS ((size_t)B_*T_*H_*DL)

// ---- scratch ----
__device__ float g_cos[T_*DH];
__device__ float g_sin[T_*DH];

__device__ __nv_bfloat16 g_xh[(size_t)B_*T_*CDIM];
__device__ __nv_bfloat16 g_xl[(size_t)B_*T_*CDIM];
__device__ __nv_bfloat16 g_yh[(size_t)B_*T_*CDIM];
__device__ __nv_bfloat16 g_yl[(size_t)B_*T_*CDIM];
__device__ __half g_qf[(size_t)B_*T_*H_*DH];
__device__ __half g_kf[(size_t)B_*T_*H_*DH];
__device__ __half g_vf[(size_t)B_*T_*H_*DH];
__device__ __nv_bfloat16 g_wh[3u*1024*1024];
__device__ __nv_bfloat16 g_wl[3u*1024*1024];
#define WQ_OFF 0u
#define WK_OFF (1024u*1024u)
#define WV_OFF (1536u*1024u)
#define WC_OFF (2048u*1024u)

// ============================================================
// PTX helpers
// ============================================================
__device__ __forceinline__ uint32_t smem_u32(const void* p) {
    uint32_t a;
    asm("{ .reg .u64 t; cvta.to.shared.u64 t, %1; cvt.u32.u64 %0, t; }"
        : "=r"(a) : "l"(p));
    return a;
}
__device__ __forceinline__ void cp16(uint32_t dst, const void* src) {
    asm volatile("cp.async.cg.shared.global [%0], [%1], 16;\n"
                 :: "r"(dst), "l"(src));
}
__device__ __forceinline__ void cp_commit() {
    asm volatile("cp.async.commit_group;\n" ::: "memory");
}
template<int N> __device__ __forceinline__ void cp_wait() {
    asm volatile("cp.async.wait_group %0;\n" :: "n"(N) : "memory");
}
__device__ __forceinline__ void ldm_x4(uint32_t* r, uint32_t addr) {
    asm volatile("ldmatrix.sync.aligned.m8n8.x4.shared.b16 {%0,%1,%2,%3}, [%4];"
        : "=r"(r[0]), "=r"(r[1]), "=r"(r[2]), "=r"(r[3]) : "r"(addr));
}
__device__ __forceinline__ void ldm_x4_t(uint32_t* r, uint32_t addr) {
    asm volatile("ldmatrix.sync.aligned.m8n8.x4.trans.shared.b16 {%0,%1,%2,%3}, [%4];"
        : "=r"(r[0]), "=r"(r[1]), "=r"(r[2]), "=r"(r[3]) : "r"(addr));
}
__device__ __forceinline__ void mma_bf16(float* c, const uint32_t* a, const uint32_t* b) {
    asm volatile("mma.sync.aligned.m16n8k16.row.col.f32.bf16.bf16.f32 "
        "{%0,%1,%2,%3}, {%4,%5,%6,%7}, {%8,%9}, {%0,%1,%2,%3};\n"
        : "+f"(c[0]), "+f"(c[1]), "+f"(c[2]), "+f"(c[3])
        : "r"(a[0]), "r"(a[1]), "r"(a[2]), "r"(a[3]), "r"(b[0]), "r"(b[1]));
}
__device__ __forceinline__ void mma_f16(float* c, const uint32_t* a, const uint32_t* b) {
    asm volatile("mma.sync.aligned.m16n8k16.row.col.f32.f16.f16.f32 "
        "{%0,%1,%2,%3}, {%4,%5,%6,%7}, {%8,%9}, {%0,%1,%2,%3};\n"
        : "+f"(c[0]), "+f"(c[1]), "+f"(c[2]), "+f"(c[3])
        : "r"(a[0]), "r"(a[1]), "r"(a[2]), "r"(a[3]), "r"(b[0]), "r"(b[1]));
}
__device__ __forceinline__ void split2(float a, float b, uint32_t& h, uint32_t& l) {
    __nv_bfloat16 ha = __float2bfloat16(a), hb = __float2bfloat16(b);
    __nv_bfloat16 la = __float2bfloat16(a - __bfloat162float(ha));
    __nv_bfloat16 lb = __float2bfloat16(b - __bfloat162float(hb));
    h = (uint32_t)__bfloat16_as_ushort(ha) | ((uint32_t)__bfloat16_as_ushort(hb) << 16);
    l = (uint32_t)__bfloat16_as_ushort(la) | ((uint32_t)__bfloat16_as_ushort(lb) << 16);
}
__device__ __forceinline__ uint32_t pack_h2(float a, float b) {
    __half2 h = __floats2half2_rn(a, b);
    return *(uint32_t*)&h;
}

// ============================================================
// split kernels (fp32 -> bf16 hi/lo)
// ============================================================
__device__ __forceinline__ void split_store4(const float4 v,
                                             uint32_t* hi, uint32_t* lo, size_t i2)
{
    uint32_t h0, l0, h1, l1;
    split2(v.x, v.y, h0, l0);
    split2(v.z, v.w, h1, l1);
    hi[i2]   = h0; hi[i2+1] = h1;
    lo[i2]   = l0; lo[i2+1] = l1;
}

__global__ void __launch_bounds__(256)
split_x_kernel(const float* __restrict__ in)
{
    int i = blockIdx.x * blockDim.x + threadIdx.x;
    float4 v = ((const float4*)in)[i];
    split_store4(v, (uint32_t*)g_xh, (uint32_t*)g_xl, 2 * (size_t)i);
}

__global__ void __launch_bounds__(256)
split_w_kernel(const float* __restrict__ Wq, const float* __restrict__ Wk,
               const float* __restrict__ Wv, const float* __restrict__ Wc)
{
    int i = blockIdx.x * blockDim.x + threadIdx.x;
    const float* src; int off;
    if      (i < 262144) { src = Wq; off = i; }
    else if (i < 393216) { src = Wk; off = i - 262144; }
    else if (i < 524288) { src = Wv; off = i - 393216; }
    else                 { src = Wc; off = i - 524288; }
    float4 v = ((const float4*)src)[off];
    split_store4(v, (uint32_t*)g_wh, (uint32_t*)g_wl, 2 * (size_t)i);
}

// ============================================================
// HMMA GEMM: 2-stage pipeline, 2 CTAs/SM, A-fragment register reuse.
// ============================================================
#define GS_ROWB   80
#define GS_MAT    (128 * GS_ROWB)
#define GS_STAGE  (4 * GS_MAT)          // 40960
#define GS_SMEM   (2 * GS_STAGE)        // 81920 -> 2 CTAs/SM

__device__ __forceinline__ void hgemm_load_chunk(
    const __nv_bfloat16* __restrict__ Ah, const __nv_bfloat16* __restrict__ Al,
    const __nv_bfloat16* __restrict__ Bh, const __nv_bfloat16* __restrict__ Bl,
    int K, int bm, int bn, int k0, uint32_t sbase, int tid)
{
#pragma unroll
    for (int i = 0; i < 8; i++) {
        int task = tid + (i << 8);
        int op   = task >> 9;
        int t2   = task & 511;
        int row  = t2 >> 2;
        int g    = t2 & 3;
        const __nv_bfloat16* base;
        int grow;
        if      (op == 0) { base = Ah; grow = bm + row; }
        else if (op == 1) { base = Al; grow = bm + row; }
        else if (op == 2) { base = Bh; grow = bn + row; }
        else              { base = Bl; grow = bn + row; }
        const void* src = base + (size_t)grow * K + k0 + (g << 3);
        uint32_t dst = sbase + op * GS_MAT + row * GS_ROWB + (g << 4);
        cp16(dst, src);
    }
}

__device__ __forceinline__ void hgemm_body(
    const __nv_bfloat16* __restrict__ Ah, const __nv_bfloat16* __restrict__ Al,
    const __nv_bfloat16* __restrict__ Bh, const __nv_bfloat16* __restrict__ Bl,
    float* __restrict__ C, int K, int N, int bm, int bn, int mode)
{
    extern __shared__ __align__(128) char sm[];
    const uint32_t smb = smem_u32(sm);
    const int tid  = threadIdx.x;
    const int wid  = tid >> 5;
    const int lane = tid & 31;
    const int wm = (wid >> 2) << 6;
    const int wn = (wid & 3) << 5;

    const int rA = (lane & 7) + ((lane >> 3) & 1) * 8;
    const int cA = (lane >> 4) << 3;
    const int rB = (lane & 7) + ((lane >> 4) << 3);
    const int cB = ((lane >> 3) & 1) << 3;

    float acc[4][4][4];
#pragma unroll
    for (int mt = 0; mt < 4; mt++)
#pragma unroll
        for (int nt = 0; nt < 4; nt++)
#pragma unroll
            for (int e = 0; e < 4; e++) acc[mt][nt][e] = 0.f;

    const int NC = K >> 5;

    hgemm_load_chunk(Ah, Al, Bh, Bl, K, bm, bn, 0, smb, tid);
    cp_commit();
    hgemm_load_chunk(Ah, Al, Bh, Bl, K, bm, bn, 32, smb + GS_STAGE, tid);
    cp_commit();

    for (int c = 0; c < NC; c++) {
        const uint32_t sb = smb + (c & 1) * GS_STAGE;
        if (c + 1 < NC) cp_wait<1>(); else cp_wait<0>();
        __syncthreads();

#pragma unroll
        for (int ks = 0; ks < 2; ks++) {
            const int k0 = ks << 4;
            uint32_t af[4][4], bh[2][4], bl[2][4];
#pragma unroll
            for (int nt2 = 0; nt2 < 2; nt2++) {
                uint32_t ro = (uint32_t)(wn + (nt2 << 4) + rB) * GS_ROWB + ((k0 + cB) << 1);
                ldm_x4(bh[nt2], sb + 2 * GS_MAT + ro);
                ldm_x4(bl[nt2], sb + 3 * GS_MAT + ro);
            }
            // pass 1+2: A-hi against B-hi and B-lo
#pragma unroll
            for (int mt = 0; mt < 4; mt++) {
                uint32_t ro = (uint32_t)(wm + (mt << 4) + rA) * GS_ROWB + ((k0 + cA) << 1);
                ldm_x4(af[mt], sb + 0 * GS_MAT + ro);
            }
#pragma unroll
            for (int mt = 0; mt < 4; mt++)
#pragma unroll
                for (int nt = 0; nt < 4; nt++)
                    mma_bf16(acc[mt][nt], af[mt], &bh[nt >> 1][(nt & 1) << 1]);
#pragma unroll
            for (int mt = 0; mt < 4; mt++)
#pragma unroll
                for (int nt = 0; nt < 4; nt++)
                    mma_bf16(acc[mt][nt], af[mt], &bl[nt >> 1][(nt & 1) << 1]);
            // pass 3: reload af with A-lo (register reuse), against B-hi
#pragma unroll
            for (int mt = 0; mt < 4; mt++) {
                uint32_t ro = (uint32_t)(wm + (mt << 4) + rA) * GS_ROWB + ((k0 + cA) << 1);
                ldm_x4(af[mt], sb + 1 * GS_MAT + ro);
            }
#pragma unroll
            for (int mt = 0; mt < 4; mt++)
#pragma unroll
                for (int nt = 0; nt < 4; nt++)
                    mma_bf16(acc[mt][nt], af[mt], &bh[nt >> 1][(nt & 1) << 1]);
        }
        __syncthreads();
        if (c + 2 < NC)
            hgemm_load_chunk(Ah, Al, Bh, Bl, K, bm, bn, (c + 2) << 5,
                             smb + (c & 1) * GS_STAGE, tid);
        cp_commit();
    }

    const int g  = lane >> 2;
    const int tg = lane & 3;
    if (mode == 0) {
#pragma unroll
        for (int mt = 0; mt < 4; mt++) {
            const int row0 = bm + wm + (mt << 4) + g;
#pragma unroll
            for (int nt = 0; nt < 4; nt++) {
                const int col = bn + wn + (nt << 3) + (tg << 1);
                *(float2*)&C[(size_t)row0 * N + col] =
                    make_float2(acc[mt][nt][0], acc[mt][nt][1]);
                *(float2*)&C[(size_t)(row0 + 8) * N + col] =
                    make_float2(acc[mt][nt][2], acc[mt][nt][3]);
            }
        }
    } else {
#pragma unroll
        for (int mt = 0; mt < 4; mt++) {
            const int row0 = bm + wm + (mt << 4) + g;
            const int t0 = row0 & (T_ - 1);
            const int t1 = (row0 + 8) & (T_ - 1);
#pragma unroll
            for (int nt = 0; nt < 4; nt++) {
                const int col = bn + wn + (nt << 3) + (tg << 1);
                const int d0 = col & 63, d1 = d0 + 1;
                float q0 = acc[mt][nt][0] * 0.125f, q1 = acc[mt][nt][1] * 0.125f;
                float c0 = g_cos[t0*DH+d0], s0 = g_sin[t0*DH+d0];
                float c1 = g_cos[t0*DH+d1], s1 = g_sin[t0*DH+d1];
                ((uint32_t*)g_qf)[((size_t)row0 * CDIM + col) >> 1] =
                    pack_h2(q0*c0 - q1*s0, q1*c1 + q0*s1);
                q0 = acc[mt][nt][2] * 0.125f; q1 = acc[mt][nt][3] * 0.125f;
                c0 = g_cos[t1*DH+d0]; s0 = g_sin[t1*DH+d0];
                c1 = g_cos[t1*DH+d1]; s1 = g_sin[t1*DH+d1];
                ((uint32_t*)g_qf)[((size_t)(row0 + 8) * CDIM + col) >> 1] =
                    pack_h2(q0*c0 - q1*s0, q1*c1 + q0*s1);
            }
        }
    }
}

__global__ void __launch_bounds__(256, 2)
proj_gemm(const __nv_bfloat16* __restrict__ xh, const __nv_bfloat16* __restrict__ xl,
          const __nv_bfloat16* __restrict__ wh, const __nv_bfloat16* __restrict__ wl,
          float* __restrict__ Ck, float* __restrict__ Cv)
{
    const int bm = blockIdx.y << 7;
    if (blockIdx.z == 0) {
        hgemm_body(xh, xl, wh + WQ_OFF, wl + WQ_OFF, nullptr,
                   CDIM, CDIM, bm, blockIdx.x << 7, 1);
    } else if (blockIdx.x < 4) {
        hgemm_body(xh, xl, wh + WK_OFF, wl + WK_OFF, Ck,
                   CDIM, 512, bm, blockIdx.x << 7, 0);
    } else {
        hgemm_body(xh, xl, wh + WV_OFF, wl + WV_OFF, Cv,
                   CDIM, 512, bm, (blockIdx.x - 4) << 7, 0);
    }
}

__global__ void __launch_bounds__(256, 2)
hgemm_wc(const __nv_bfloat16* __restrict__ Ah, const __nv_bfloat16* __restrict__ Al,
         const __nv_bfloat16* __restrict__ Bh, const __nv_bfloat16* __restrict__ Bl,
         float* __restrict__ C)
{
    hgemm_body(Ah, Al, Bh, Bl, C, CDIM, CDIM, blockIdx.y << 7, blockIdx.x << 7, 0);
}

// ============================================================
// RoPE table
// ============================================================
__global__ void rope_table_kernel() {
    int t = blockIdx.x;
    int c = threadIdx.x;
    int j = c & 31;
    double inv = pow(10000.0, -(double)j / 32.0);
    float  ang = (float)t * (float)inv;
    double s, cc;
    sincos((double)ang, &s, &cc);
    g_cos[t * DH + c] = (float)cc;
    g_sin[t * DH + c] = (float)s;
}

// ============================================================
// Up-projection + RoPE for k, v -> fp16. 4 tokens per CTA.
// ============================================================
__global__ void __launch_bounds__(256)
upproj_rope_kernel(const float* __restrict__ klat, const float* __restrict__ vlat,
                   const float* __restrict__ Wku,  const float* __restrict__ Wvu)
{
    const int bt0 = blockIdx.x << 2;
    __shared__ float skl[2048], svl[2048];
    __shared__ float swk[64 * 33], swv[64 * 33];
    const int tid = threadIdx.x;

    for (int u = tid; u < 512; u += 256) {
        ((float4*)skl)[u] = ((const float4*)(klat + (size_t)bt0 * 512))[u];
        ((float4*)svl)[u] = ((const float4*)(vlat + (size_t)bt0 * 512))[u];
    }
    for (int i = tid; i < 64 * 32; i += 256) {
        int d = i >> 5, l = i & 31;
        swk[d * 33 + l] = Wku[i];
        swv[d * 33 + l] = Wvu[i];
    }
    __syncthreads();

#pragma unroll
    for (int u = 0; u < 8; u++) {
        const int unit = tid + (u << 8);
        const int tok = unit >> 9;
        const int p   = unit & 511;
        const int h  = p >> 5, i = p & 31;
        const int d0 = i << 1, d1 = d0 + 1;
        const int bt = bt0 + tok;
        const int t  = bt & (T_ - 1);
        const float* kl  = &skl[(tok << 9) + (h << 5)];
        const float* vl  = &svl[(tok << 9) + (h << 5)];
        const float* wk0 = &swk[d0 * 33];
        const float* wk1 = &swk[d1 * 33];
        const float* wv0 = &swv[d0 * 33];
        const float* wv1 = &swv[d1 * 33];
        float k0 = 0.f, k1 = 0.f, v0 = 0.f, v1 = 0.f;
#pragma unroll
        for (int l = 0; l < 32; l++) {
            float klv = kl[l], vlv = vl[l];
            k0 = fmaf(klv, wk0[l], k0);
            k1 = fmaf(klv, wk1[l], k1);
            v0 = fmaf(vlv, wv0[l], v0);
            v1 = fmaf(vlv, wv1[l], v1);
        }
        const float c0 = g_cos[t * DH + d0], s0 = g_sin[t * DH + d0];
        const float c1 = g_cos[t * DH + d1], s1 = g_sin[t * DH + d1];
        const size_t pi = (((size_t)bt * H_ + h) * DH + d0) >> 1;
        ((uint32_t*)g_kf)[pi] = pack_h2(k0 * c0 - k1 * s0, k1 * c1 + k0 * s1);
        ((uint32_t*)g_vf)[pi] = pack_h2(v0, v1);
    }
}

// ============================================================
// fp16 HMMA causal flash attention, 3-buffer single-sync KV
// pipeline, 2 CTAs/SM.
// ============================================================
#define AT_ROWB   144
#define AT_MAT    (64 * AT_ROWB)
#define AT_STAGE  (2 * AT_MAT)
#define AT_QOFF   (3 * AT_STAGE)
#define AT_QMAT   (128 * AT_ROWB)
#define AT_SMEM   (AT_QOFF + AT_QMAT)   // 73728

__device__ __forceinline__ void attn_load_kv(int b, int h, int kb,
                                             uint32_t sbase, int tid)
{
    const int k0 = kb << 6;
#pragma unroll
    for (int i = 0; i < 4; i++) {
        int task = tid + (i << 8);
        int op = task >> 9;
        int t2 = task & 511;
        int row = t2 >> 3, g = t2 & 7;
        const __half* base = op ? g_vf : g_kf;
        const void* src = base + ((size_t)(b * T_ + k0 + row) * H_ + h) * DH + (g << 3);
        cp16(sbase + op * AT_MAT + row * AT_ROWB + (g << 4), src);
    }
}

__global__ void __launch_bounds__(256, 2)
attn_mma_kernel()
{
    extern __shared__ __align__(128) char sm[];
    const uint32_t smb = smem_u32(sm);
    const int tid = threadIdx.x;
    const int wid = tid >> 5, lane = tid & 31;
    const int qt = gridDim.x - 1 - blockIdx.x;
    const int h = blockIdx.y, b = blockIdx.z;
    const int q0 = qt << 7;
    const int nkb = 2 * qt + 2;
    const int g = lane >> 2, tg = lane & 3;

#pragma unroll
    for (int i = 0; i < 4; i++) {
        int task = tid + (i << 8);
        int row = task >> 3, gg = task & 7;
        const void* src = g_qf + ((size_t)(b * T_ + q0 + row) * H_ + h) * DH + (gg << 3);
        cp16(smb + AT_QOFF + row * AT_ROWB + (gg << 4), src);
    }
    cp_commit();
    attn_load_kv(b, h, 0, smb, tid);
    cp_commit();
    attn_load_kv(b, h, 1, smb + AT_STAGE, tid);
    cp_commit();

    cp_wait<2>();
    __syncthreads();
    const int rA = (lane & 7) + ((lane >> 3) & 1) * 8;
    const int cA = (lane >> 4) << 3;
    uint32_t qf[4][4];
#pragma unroll
    for (int kf = 0; kf < 4; kf++) {
        uint32_t ro = (uint32_t)(wid * 16 + rA) * AT_ROWB + ((kf * 16 + cA) << 1);
        ldm_x4(qf[kf], smb + AT_QOFF + ro);
    }

    const int rB = (lane & 7) + ((lane >> 4) << 3);
    const int cB = ((lane >> 3) & 1) << 3;
    const int rV = lane & 15;
    const int cV = (lane >> 4) << 4;

    float yacc[8][4];
#pragma unroll
    for (int i = 0; i < 8; i++)
#pragma unroll
        for (int e = 0; e < 4; e++) yacc[i][e] = 0.f;
    float m0 = -1e30f, m1 = -1e30f, l0 = 0.f, l1 = 0.f;

    int bc = 0, bp = 2;
    for (int kb = 0; kb < nkb; kb++) {
        cp_wait<1>();
        __syncthreads();
        if (kb + 2 < nkb)
            attn_load_kv(b, h, kb + 2, smb + bp * AT_STAGE, tid);
        cp_commit();
        const uint32_t sb = smb + bc * AT_STAGE;
        bc = (bc == 2) ? 0 : bc + 1;
        bp = (bp == 2) ? 0 : bp + 1;

        float s[8][4];
#pragma unroll
        for (int i = 0; i < 8; i++)
#pragma unroll
            for (int e = 0; e < 4; e++) s[i][e] = 0.f;
#pragma unroll
        for (int kf = 0; kf < 4; kf++) {
#pragma unroll
            for (int nt16 = 0; nt16 < 4; nt16++) {
                uint32_t ro = (uint32_t)(nt16 * 16 + rB) * AT_ROWB + ((kf * 16 + cB) << 1);
                uint32_t bk[4];
                ldm_x4(bk, sb + ro);
                mma_f16(s[nt16 * 2],     qf[kf], &bk[0]);
                mma_f16(s[nt16 * 2 + 1], qf[kf], &bk[2]);
            }
        }

        if (kb >= 2 * qt) {
            const int row0 = q0 + wid * 16 + g;
#pragma unroll
            for (int nt = 0; nt < 8; nt++) {
                const int col0 = (kb << 6) + nt * 8 + (tg << 1);
                if (col0     > row0)     s[nt][0] = -1e30f;
                if (col0 + 1 > row0)     s[nt][1] = -1e30f;
                if (col0     > row0 + 8) s[nt][2] = -1e30f;
                if (col0 + 1 > row0 + 8) s[nt][3] = -1e30f;
            }
        }

        float mx0 = -1e30f, mx1 = -1e30f;
#pragma unroll
        for (int nt = 0; nt < 8; nt++) {
            mx0 = fmaxf(mx0, fmaxf(s[nt][0], s[nt][1]));
            mx1 = fmaxf(mx1, fmaxf(s[nt][2], s[nt][3]));
        }
        mx0 = fmaxf(mx0, __shfl_xor_sync(0xffffffffu, mx0, 1));
        mx0 = fmaxf(mx0, __shfl_xor_sync(0xffffffffu, mx0, 2));
        mx1 = fmaxf(mx1, __shfl_xor_sync(0xffffffffu, mx1, 1));
        mx1 = fmaxf(mx1, __shfl_xor_sync(0xffffffffu, mx1, 2));
        const float mn0 = fmaxf(m0, mx0), mn1 = fmaxf(m1, mx1);
        const float a0 = __expf(m0 - mn0), a1 = __expf(m1 - mn1);
        m0 = mn0; m1 = mn1;
        float r0 = 0.f, r1 = 0.f;
#pragma unroll
        for (int nt = 0; nt < 8; nt++) {
            s[nt][0] = __expf(s[nt][0] - mn0);
            s[nt][1] = __expf(s[nt][1] - mn0);
            s[nt][2] = __expf(s[nt][2] - mn1);
            s[nt][3] = __expf(s[nt][3] - mn1);
            r0 += s[nt][0] + s[nt][1];
            r1 += s[nt][2] + s[nt][3];
        }
        r0 += __shfl_xor_sync(0xffffffffu, r0, 1);
        r0 += __shfl_xor_sync(0xffffffffu, r0, 2);
        r1 += __shfl_xor_sync(0xffffffffu, r1, 1);
        r1 += __shfl_xor_sync(0xffffffffu, r1, 2);
        l0 = l0 * a0 + r0;
        l1 = l1 * a1 + r1;
#pragma unroll
        for (int i = 0; i < 8; i++) {
            yacc[i][0] *= a0; yacc[i][1] *= a0;
            yacc[i][2] *= a1; yacc[i][3] *= a1;
        }

#pragma unroll
        for (int kf = 0; kf < 4; kf++) {
            uint32_t ph[4];
            ph[0] = pack_h2(s[2*kf][0],   s[2*kf][1]);
            ph[1] = pack_h2(s[2*kf][2],   s[2*kf][3]);
            ph[2] = pack_h2(s[2*kf+1][0], s[2*kf+1][1]);
            ph[3] = pack_h2(s[2*kf+1][2], s[2*kf+1][3]);
#pragma unroll
            for (int dt = 0; dt < 4; dt++) {
                uint32_t vh[4];
                uint32_t ro = (uint32_t)(kf * 16 + rV) * AT_ROWB + dt * 32 + cV;
                ldm_x4_t(vh, sb + AT_MAT + ro);
                mma_f16(yacc[dt * 2],     ph, &vh[0]);
                mma_f16(yacc[dt * 2 + 1], ph, &vh[2]);
            }
        }
    }

    const float il0 = 1.f / l0, il1 = 1.f / l1;
    const int row0 = q0 + wid * 16 + g;
#pragma unroll
    for (int dt8 = 0; dt8 < 8; dt8++) {
        const int col = h * 64 + dt8 * 8 + (tg << 1);
        uint32_t hw, lw;
        split2(yacc[dt8][0] * il0, yacc[dt8][1] * il0, hw, lw);
        size_t o0 = ((size_t)(b * T_ + row0) * CDIM + col) >> 1;
        ((uint32_t*)g_yh)[o0] = hw; ((uint32_t*)g_yl)[o0] = lw;
        split2(yacc[dt8][2] * il1, yacc[dt8][3] * il1, hw, lw);
        size_t o1 = ((size_t)(b * T_ + row0 + 8) * CDIM + col) >> 1;
        ((uint32_t*)g_yh)[o1] = hw; ((uint32_t*)g_yl)[o1] = lw;
    }
}

// ============================================================
// launch
// ============================================================
extern "C" void kernel_launch(void* const* d_in, const int* in_sizes, int n_in,
                              void* d_out, int out_size)
{
    const float* x   = (const float*)d_in[0];
    const float* Wq  = (const float*)d_in[1];
    const float* Wk  = (const float*)d_in[2];
    const float* Wv  = (const float*)d_in[3];
    const float* Wku = (const float*)d_in[4];
    const float* Wvu = (const float*)d_in[5];
    const float* Wc  = (const float*)d_in[6];

    float* out      = (float*)d_out;
    float* y_out    = out;
    float* klat_out = out + Y_ELEMS;
    float* vlat_out = out + Y_ELEMS + KL_ELEMS;

    __nv_bfloat16 *xh, *xl, *yh, *yl, *wh, *wl;
    cudaGetSymbolAddress((void**)&xh, g_xh);
    cudaGetSymbolAddress((void**)&xl, g_xl);
    cudaGetSymbolAddress((void**)&yh, g_yh);
    cudaGetSymbolAddress((void**)&yl, g_yl);
    cudaGetSymbolAddress((void**)&wh, g_wh);
    cudaGetSymbolAddress((void**)&wl, g_wl);

    cudaFuncSetAttribute(attn_mma_kernel, cudaFuncAttributeMaxDynamicSharedMemorySize, AT_SMEM);
    cudaFuncSetAttribute(proj_gemm, cudaFuncAttributeMaxDynamicSharedMemorySize, GS_SMEM);
    cudaFuncSetAttribute(hgemm_wc, cudaFuncAttributeMaxDynamicSharedMemorySize, GS_SMEM);

    rope_table_kernel<<<T_, 64>>>();
    split_x_kernel<<<4096, 256>>>(x);
    split_w_kernel<<<3072, 256>>>(Wq, Wk, Wv, Wc);

    dim3 gp(8, (B_ * T_) / 128, 2);
    proj_gemm<<<gp, 256, GS_SMEM>>>(xh, xl, wh, wl, klat_out, vlat_out);

    upproj_rope_kernel<<<B_ * T_ / 4, 256>>>(klat_out, vlat_out, Wku, Wvu);

    dim3 ga(T_ / 128, H_, B_);
    attn_mma_kernel<<<ga, 256, AT_SMEM>>>();

    dim3 gc(8, (B_ * T_) / 128);
    hgemm_wc<<<gc, 256, GS_SMEM>>>(yh, yl, wh + WC_OFF, wl + WC_OFF, y_out);
}

// round 8
// speedup vs baseline: 5.5830x; 1.5538x over previous
#include <cuda_runtime.h>
#include <cuda_bf16.h>
#include <cuda_fp16.h>
#include <math.h>
#include <stdint.h>

#define B_   2
#define T_   2048
#define H_   16
#define DH   64
#define DL   32
#define CDIM 1024

#define Y_ELEMS  ((size_t)B_*T_*CDIM)
#define KL_ELEMS ((size_t)B_*T_*H_*DL)

// ---- scratch ----
__device__ float g_cos[T_*DH];
__device__ float g_sin[T_*DH];

__device__ __half g_xf[(size_t)B_*T_*CDIM];     // fp16 x
__device__ __half g_yf[(size_t)B_*T_*CDIM];     // fp16 attention out
__device__ __half g_qf[(size_t)B_*T_*H_*DH];
__device__ __half g_kf[(size_t)B_*T_*H_*DH];
__device__ __half g_vf[(size_t)B_*T_*H_*DH];
// fp16 weights packed: Wq @0 (1M), Wk @1M (0.5M), Wv @1.5M (0.5M), Wc @2M (1M)
__device__ __half g_wf[3u*1024*1024];
#define WQ_OFF 0u
#define WK_OFF (1024u*1024u)
#define WV_OFF (1536u*1024u)
#define WC_OFF (2048u*1024u)

// ============================================================
// PTX helpers
// ============================================================
__device__ __forceinline__ uint32_t smem_u32(const void* p) {
    uint32_t a;
    asm("{ .reg .u64 t; cvta.to.shared.u64 t, %1; cvt.u32.u64 %0, t; }"
        : "=r"(a) : "l"(p));
    return a;
}
__device__ __forceinline__ void cp16(uint32_t dst, const void* src) {
    asm volatile("cp.async.cg.shared.global [%0], [%1], 16;\n"
                 :: "r"(dst), "l"(src));
}
__device__ __forceinline__ void cp_commit() {
    asm volatile("cp.async.commit_group;\n" ::: "memory");
}
template<int N> __device__ __forceinline__ void cp_wait() {
    asm volatile("cp.async.wait_group %0;\n" :: "n"(N) : "memory");
}
__device__ __forceinline__ void ldm_x4(uint32_t* r, uint32_t addr) {
    asm volatile("ldmatrix.sync.aligned.m8n8.x4.shared.b16 {%0,%1,%2,%3}, [%4];"
        : "=r"(r[0]), "=r"(r[1]), "=r"(r[2]), "=r"(r[3]) : "r"(addr));
}
__device__ __forceinline__ void ldm_x4_t(uint32_t* r, uint32_t addr) {
    asm volatile("ldmatrix.sync.aligned.m8n8.x4.trans.shared.b16 {%0,%1,%2,%3}, [%4];"
        : "=r"(r[0]), "=r"(r[1]), "=r"(r[2]), "=r"(r[3]) : "r"(addr));
}
__device__ __forceinline__ void mma_f16(float* c, const uint32_t* a, const uint32_t* b) {
    asm volatile("mma.sync.aligned.m16n8k16.row.col.f32.f16.f16.f32 "
        "{%0,%1,%2,%3}, {%4,%5,%6,%7}, {%8,%9}, {%0,%1,%2,%3};\n"
        : "+f"(c[0]), "+f"(c[1]), "+f"(c[2]), "+f"(c[3])
        : "r"(a[0]), "r"(a[1]), "r"(a[2]), "r"(a[3]), "r"(b[0]), "r"(b[1]));
}
__device__ __forceinline__ uint32_t pack_h2(float a, float b) {
    __half2 h = __floats2half2_rn(a, b);
    return *(uint32_t*)&h;
}

// ============================================================
// fp32 -> fp16 convert kernels
// ============================================================
__global__ void __launch_bounds__(256)
cvt_x_kernel(const float* __restrict__ in)
{
    int i = blockIdx.x * blockDim.x + threadIdx.x;
    float4 v = ((const float4*)in)[i];
    ((uint32_t*)g_xf)[2*i]   = pack_h2(v.x, v.y);
    ((uint32_t*)g_xf)[2*i+1] = pack_h2(v.z, v.w);
}

__global__ void __launch_bounds__(256)
cvt_w_kernel(const float* __restrict__ Wq, const float* __restrict__ Wk,
             const float* __restrict__ Wv, const float* __restrict__ Wc)
{
    int i = blockIdx.x * blockDim.x + threadIdx.x;
    const float* src; int off;
    if      (i < 262144) { src = Wq; off = i; }
    else if (i < 393216) { src = Wk; off = i - 262144; }
    else if (i < 524288) { src = Wv; off = i - 393216; }
    else                 { src = Wc; off = i - 524288; }
    float4 v = ((const float4*)src)[off];
    ((uint32_t*)g_wf)[2*i]   = pack_h2(v.x, v.y);
    ((uint32_t*)g_wf)[2*i+1] = pack_h2(v.z, v.w);
}

// ============================================================
// fp16 HMMA GEMM: C = A @ W^T. 3-stage single-sync pipeline,
// 2 CTAs/SM. A:[M,K] fp16, W:[N,K] fp16 (K-contig).
// ============================================================
#define GS_ROWB   80
#define GS_MAT    (128 * GS_ROWB)       // 10240
#define GS_STAGE  (2 * GS_MAT)          // 20480 (A, B)
#define GS_SMEM   (3 * GS_STAGE)        // 61440 -> 2 CTAs/SM easily

__device__ __forceinline__ void hgemm_load_chunk(
    const __half* __restrict__ A, const __half* __restrict__ B,
    int K, int bm, int bn, int k0, uint32_t sbase, int tid)
{
#pragma unroll
    for (int i = 0; i < 4; i++) {
        int task = tid + (i << 8);      // 1024: op(2) x row(128) x granule(4)
        int op   = task >> 9;
        int t2   = task & 511;
        int row  = t2 >> 2;
        int g    = t2 & 3;
        const __half* base = op ? B : A;
        int grow = (op ? bn : bm) + row;
        const void* src = base + (size_t)grow * K + k0 + (g << 3);
        uint32_t dst = sbase + op * GS_MAT + row * GS_ROWB + (g << 4);
        cp16(dst, src);
    }
}

__device__ __forceinline__ void hgemm_body(
    const __half* __restrict__ A, const __half* __restrict__ B,
    float* __restrict__ C, int K, int N, int bm, int bn, int mode)
{
    extern __shared__ __align__(128) char sm[];
    const uint32_t smb = smem_u32(sm);
    const int tid  = threadIdx.x;
    const int wid  = tid >> 5;
    const int lane = tid & 31;
    const int wm = (wid >> 2) << 6;
    const int wn = (wid & 3) << 5;

    const int rA = (lane & 7) + ((lane >> 3) & 1) * 8;
    const int cA = (lane >> 4) << 3;
    const int rB = (lane & 7) + ((lane >> 4) << 3);
    const int cB = ((lane >> 3) & 1) << 3;

    float acc[4][4][4];
#pragma unroll
    for (int mt = 0; mt < 4; mt++)
#pragma unroll
        for (int nt = 0; nt < 4; nt++)
#pragma unroll
            for (int e = 0; e < 4; e++) acc[mt][nt][e] = 0.f;

    const int NC = K >> 5;

    hgemm_load_chunk(A, B, K, bm, bn, 0, smb, tid);
    cp_commit();
    hgemm_load_chunk(A, B, K, bm, bn, 32, smb + GS_STAGE, tid);
    cp_commit();

    int bc = 0, bp = 2;
    for (int c = 0; c < NC; c++) {
        cp_wait<1>();
        __syncthreads();
        if (c + 2 < NC)
            hgemm_load_chunk(A, B, K, bm, bn, (c + 2) << 5,
                             smb + bp * GS_STAGE, tid);
        cp_commit();
        const uint32_t sb = smb + bc * GS_STAGE;
        bc = (bc == 2) ? 0 : bc + 1;
        bp = (bp == 2) ? 0 : bp + 1;

#pragma unroll
        for (int ks = 0; ks < 2; ks++) {
            const int k0 = ks << 4;
            uint32_t af[4][4], bf[2][4];
#pragma unroll
            for (int mt = 0; mt < 4; mt++) {
                uint32_t ro = (uint32_t)(wm + (mt << 4) + rA) * GS_ROWB + ((k0 + cA) << 1);
                ldm_x4(af[mt], sb + ro);
            }
#pragma unroll
            for (int nt2 = 0; nt2 < 2; nt2++) {
                uint32_t ro = (uint32_t)(wn + (nt2 << 4) + rB) * GS_ROWB + ((k0 + cB) << 1);
                ldm_x4(bf[nt2], sb + GS_MAT + ro);
            }
#pragma unroll
            for (int mt = 0; mt < 4; mt++)
#pragma unroll
                for (int nt = 0; nt < 4; nt++)
                    mma_f16(acc[mt][nt], af[mt], &bf[nt >> 1][(nt & 1) << 1]);
        }
    }

    const int g  = lane >> 2;
    const int tg = lane & 3;
    if (mode == 0) {
#pragma unroll
        for (int mt = 0; mt < 4; mt++) {
            const int row0 = bm + wm + (mt << 4) + g;
#pragma unroll
            for (int nt = 0; nt < 4; nt++) {
                const int col = bn + wn + (nt << 3) + (tg << 1);
                *(float2*)&C[(size_t)row0 * N + col] =
                    make_float2(acc[mt][nt][0], acc[mt][nt][1]);
                *(float2*)&C[(size_t)(row0 + 8) * N + col] =
                    make_float2(acc[mt][nt][2], acc[mt][nt][3]);
            }
        }
    } else {
        // rope + 0.125 scale -> g_qf (fp16)
#pragma unroll
        for (int mt = 0; mt < 4; mt++) {
            const int row0 = bm + wm + (mt << 4) + g;
            const int t0 = row0 & (T_ - 1);
            const int t1 = (row0 + 8) & (T_ - 1);
#pragma unroll
            for (int nt = 0; nt < 4; nt++) {
                const int col = bn + wn + (nt << 3) + (tg << 1);
                const int d0 = col & 63, d1 = d0 + 1;
                float q0 = acc[mt][nt][0] * 0.125f, q1 = acc[mt][nt][1] * 0.125f;
                float c0 = g_cos[t0*DH+d0], s0 = g_sin[t0*DH+d0];
                float c1 = g_cos[t0*DH+d1], s1 = g_sin[t0*DH+d1];
                ((uint32_t*)g_qf)[((size_t)row0 * CDIM + col) >> 1] =
                    pack_h2(q0*c0 - q1*s0, q1*c1 + q0*s1);
                q0 = acc[mt][nt][2] * 0.125f; q1 = acc[mt][nt][3] * 0.125f;
                c0 = g_cos[t1*DH+d0]; s0 = g_sin[t1*DH+d0];
                c1 = g_cos[t1*DH+d1]; s1 = g_sin[t1*DH+d1];
                ((uint32_t*)g_qf)[((size_t)(row0 + 8) * CDIM + col) >> 1] =
                    pack_h2(q0*c0 - q1*s0, q1*c1 + q0*s1);
            }
        }
    }
}

__global__ void __launch_bounds__(256, 2)
proj_gemm(const __half* __restrict__ xf, const __half* __restrict__ wf,
          float* __restrict__ Ck, float* __restrict__ Cv)
{
    const int bm = blockIdx.y << 7;
    if (blockIdx.z == 0) {
        hgemm_body(xf, wf + WQ_OFF, nullptr, CDIM, CDIM, bm, blockIdx.x << 7, 1);
    } else if (blockIdx.x < 4) {
        hgemm_body(xf, wf + WK_OFF, Ck, CDIM, 512, bm, blockIdx.x << 7, 0);
    } else {
        hgemm_body(xf, wf + WV_OFF, Cv, CDIM, 512, bm, (blockIdx.x - 4) << 7, 0);
    }
}

__global__ void __launch_bounds__(256, 2)
hgemm_wc(const __half* __restrict__ A, const __half* __restrict__ B,
         float* __restrict__ C)
{
    hgemm_body(A, B, C, CDIM, CDIM, blockIdx.y << 7, blockIdx.x << 7, 0);
}

// ============================================================
// RoPE table
// ============================================================
__global__ void rope_table_kernel() {
    int t = blockIdx.x;
    int c = threadIdx.x;
    int j = c & 31;
    double inv = pow(10000.0, -(double)j / 32.0);
    float  ang = (float)t * (float)inv;
    double s, cc;
    sincos((double)ang, &s, &cc);
    g_cos[t * DH + c] = (float)cc;
    g_sin[t * DH + c] = (float)s;
}

// ============================================================
// Up-projection + RoPE for k, v -> fp16. 4 tokens per CTA.
// ============================================================
__global__ void __launch_bounds__(256)
upproj_rope_kernel(const float* __restrict__ klat, const float* __restrict__ vlat,
                   const float* __restrict__ Wku,  const float* __restrict__ Wvu)
{
    const int bt0 = blockIdx.x << 2;
    __shared__ float skl[2048], svl[2048];
    __shared__ float swk[64 * 33], swv[64 * 33];
    const int tid = threadIdx.x;

    for (int u = tid; u < 512; u += 256) {
        ((float4*)skl)[u] = ((const float4*)(klat + (size_t)bt0 * 512))[u];
        ((float4*)svl)[u] = ((const float4*)(vlat + (size_t)bt0 * 512))[u];
    }
    for (int i = tid; i < 64 * 32; i += 256) {
        int d = i >> 5, l = i & 31;
        swk[d * 33 + l] = Wku[i];
        swv[d * 33 + l] = Wvu[i];
    }
    __syncthreads();

#pragma unroll
    for (int u = 0; u < 8; u++) {
        const int unit = tid + (u << 8);
        const int tok = unit >> 9;
        const int p   = unit & 511;
        const int h  = p >> 5, i = p & 31;
        const int d0 = i << 1, d1 = d0 + 1;
        const int bt = bt0 + tok;
        const int t  = bt & (T_ - 1);
        const float* kl  = &skl[(tok << 9) + (h << 5)];
        const float* vl  = &svl[(tok << 9) + (h << 5)];
        const float* wk0 = &swk[d0 * 33];
        const float* wk1 = &swk[d1 * 33];
        const float* wv0 = &swv[d0 * 33];
        const float* wv1 = &swv[d1 * 33];
        float k0 = 0.f, k1 = 0.f, v0 = 0.f, v1 = 0.f;
#pragma unroll
        for (int l = 0; l < 32; l++) {
            float klv = kl[l], vlv = vl[l];
            k0 = fmaf(klv, wk0[l], k0);
            k1 = fmaf(klv, wk1[l], k1);
            v0 = fmaf(vlv, wv0[l], v0);
            v1 = fmaf(vlv, wv1[l], v1);
        }
        const float c0 = g_cos[t * DH + d0], s0 = g_sin[t * DH + d0];
        const float c1 = g_cos[t * DH + d1], s1 = g_sin[t * DH + d1];
        const size_t pi = (((size_t)bt * H_ + h) * DH + d0) >> 1;
        ((uint32_t*)g_kf)[pi] = pack_h2(k0 * c0 - k1 * s0, k1 * c1 + k0 * s1);
        ((uint32_t*)g_vf)[pi] = pack_h2(v0, v1);
    }
}

// ============================================================
// fp16 HMMA causal flash attention (unchanged from R7)
// ============================================================
#define AT_ROWB   144
#define AT_MAT    (64 * AT_ROWB)
#define AT_STAGE  (2 * AT_MAT)
#define AT_QOFF   (3 * AT_STAGE)
#define AT_QMAT   (128 * AT_ROWB)
#define AT_SMEM   (AT_QOFF + AT_QMAT)   // 73728

__device__ __forceinline__ void attn_load_kv(int b, int h, int kb,
                                             uint32_t sbase, int tid)
{
    const int k0 = kb << 6;
#pragma unroll
    for (int i = 0; i < 4; i++) {
        int task = tid + (i << 8);
        int op = task >> 9;
        int t2 = task & 511;
        int row = t2 >> 3, g = t2 & 7;
        const __half* base = op ? g_vf : g_kf;
        const void* src = base + ((size_t)(b * T_ + k0 + row) * H_ + h) * DH + (g << 3);
        cp16(sbase + op * AT_MAT + row * AT_ROWB + (g << 4), src);
    }
}

__global__ void __launch_bounds__(256, 2)
attn_mma_kernel()
{
    extern __shared__ __align__(128) char sm[];
    const uint32_t smb = smem_u32(sm);
    const int tid = threadIdx.x;
    const int wid = tid >> 5, lane = tid & 31;
    const int qt = gridDim.x - 1 - blockIdx.x;
    const int h = blockIdx.y, b = blockIdx.z;
    const int q0 = qt << 7;
    const int nkb = 2 * qt + 2;
    const int g = lane >> 2, tg = lane & 3;

#pragma unroll
    for (int i = 0; i < 4; i++) {
        int task = tid + (i << 8);
        int row = task >> 3, gg = task & 7;
        const void* src = g_qf + ((size_t)(b * T_ + q0 + row) * H_ + h) * DH + (gg << 3);
        cp16(smb + AT_QOFF + row * AT_ROWB + (gg << 4), src);
    }
    cp_commit();
    attn_load_kv(b, h, 0, smb, tid);
    cp_commit();
    attn_load_kv(b, h, 1, smb + AT_STAGE, tid);
    cp_commit();

    cp_wait<2>();
    __syncthreads();
    const int rA = (lane & 7) + ((lane >> 3) & 1) * 8;
    const int cA = (lane >> 4) << 3;
    uint32_t qf[4][4];
#pragma unroll
    for (int kf = 0; kf < 4; kf++) {
        uint32_t ro = (uint32_t)(wid * 16 + rA) * AT_ROWB + ((kf * 16 + cA) << 1);
        ldm_x4(qf[kf], smb + AT_QOFF + ro);
    }

    const int rB = (lane & 7) + ((lane >> 4) << 3);
    const int cB = ((lane >> 3) & 1) << 3;
    const int rV = lane & 15;
    const int cV = (lane >> 4) << 4;

    float yacc[8][4];
#pragma unroll
    for (int i = 0; i < 8; i++)
#pragma unroll
        for (int e = 0; e < 4; e++) yacc[i][e] = 0.f;
    float m0 = -1e30f, m1 = -1e30f, l0 = 0.f, l1 = 0.f;

    int bc = 0, bp = 2;
    for (int kb = 0; kb < nkb; kb++) {
        cp_wait<1>();
        __syncthreads();
        if (kb + 2 < nkb)
            attn_load_kv(b, h, kb + 2, smb + bp * AT_STAGE, tid);
        cp_commit();
        const uint32_t sb = smb + bc * AT_STAGE;
        bc = (bc == 2) ? 0 : bc + 1;
        bp = (bp == 2) ? 0 : bp + 1;

        float s[8][4];
#pragma unroll
        for (int i = 0; i < 8; i++)
#pragma unroll
            for (int e = 0; e < 4; e++) s[i][e] = 0.f;
#pragma unroll
        for (int kf = 0; kf < 4; kf++) {
#pragma unroll
            for (int nt16 = 0; nt16 < 4; nt16++) {
                uint32_t ro = (uint32_t)(nt16 * 16 + rB) * AT_ROWB + ((kf * 16 + cB) << 1);
                uint32_t bk[4];
                ldm_x4(bk, sb + ro);
                mma_f16(s[nt16 * 2],     qf[kf], &bk[0]);
                mma_f16(s[nt16 * 2 + 1], qf[kf], &bk[2]);
            }
        }

        if (kb >= 2 * qt) {
            const int row0 = q0 + wid * 16 + g;
#pragma unroll
            for (int nt = 0; nt < 8; nt++) {
                const int col0 = (kb << 6) + nt * 8 + (tg << 1);
                if (col0     > row0)     s[nt][0] = -1e30f;
                if (col0 + 1 > row0)     s[nt][1] = -1e30f;
                if (col0     > row0 + 8) s[nt][2] = -1e30f;
                if (col0 + 1 > row0 + 8) s[nt][3] = -1e30f;
            }
        }

        float mx0 = -1e30f, mx1 = -1e30f;
#pragma unroll
        for (int nt = 0; nt < 8; nt++) {
            mx0 = fmaxf(mx0, fmaxf(s[nt][0], s[nt][1]));
            mx1 = fmaxf(mx1, fmaxf(s[nt][2], s[nt][3]));
        }
        mx0 = fmaxf(mx0, __shfl_xor_sync(0xffffffffu, mx0, 1));
        mx0 = fmaxf(mx0, __shfl_xor_sync(0xffffffffu, mx0, 2));
        mx1 = fmaxf(mx1, __shfl_xor_sync(0xffffffffu, mx1, 1));
        mx1 = fmaxf(mx1, __shfl_xor_sync(0xffffffffu, mx1, 2));
        const float mn0 = fmaxf(m0, mx0), mn1 = fmaxf(m1, mx1);
        const float a0 = __expf(m0 - mn0), a1 = __expf(m1 - mn1);
        m0 = mn0; m1 = mn1;
        float r0 = 0.f, r1 = 0.f;
#pragma unroll
        for (int nt = 0; nt < 8; nt++) {
            s[nt][0] = __expf(s[nt][0] - mn0);
            s[nt][1] = __expf(s[nt][1] - mn0);
            s[nt][2] = __expf(s[nt][2] - mn1);
            s[nt][3] = __expf(s[nt][3] - mn1);
            r0 += s[nt][0] + s[nt][1];
            r1 += s[nt][2] + s[nt][3];
        }
        r0 += __shfl_xor_sync(0xffffffffu, r0, 1);
        r0 += __shfl_xor_sync(0xffffffffu, r0, 2);
        r1 += __shfl_xor_sync(0xffffffffu, r1, 1);
        r1 += __shfl_xor_sync(0xffffffffu, r1, 2);
        l0 = l0 * a0 + r0;
        l1 = l1 * a1 + r1;
#pragma unroll
        for (int i = 0; i < 8; i++) {
            yacc[i][0] *= a0; yacc[i][1] *= a0;
            yacc[i][2] *= a1; yacc[i][3] *= a1;
        }

#pragma unroll
        for (int kf = 0; kf < 4; kf++) {
            uint32_t ph[4];
            ph[0] = pack_h2(s[2*kf][0],   s[2*kf][1]);
            ph[1] = pack_h2(s[2*kf][2],   s[2*kf][3]);
            ph[2] = pack_h2(s[2*kf+1][0], s[2*kf+1][1]);
            ph[3] = pack_h2(s[2*kf+1][2], s[2*kf+1][3]);
#pragma unroll
            for (int dt = 0; dt < 4; dt++) {
                uint32_t vh[4];
                uint32_t ro = (uint32_t)(kf * 16 + rV) * AT_ROWB + dt * 32 + cV;
                ldm_x4_t(vh, sb + AT_MAT + ro);
                mma_f16(yacc[dt * 2],     ph, &vh[0]);
                mma_f16(yacc[dt * 2 + 1], ph, &vh[2]);
            }
        }
    }

    // epilogue: fp16 y for Wc GEMM
    const float il0 = 1.f / l0, il1 = 1.f / l1;
    const int row0 = q0 + wid * 16 + g;
#pragma unroll
    for (int dt8 = 0; dt8 < 8; dt8++) {
        const int col = h * 64 + dt8 * 8 + (tg << 1);
        ((uint32_t*)g_yf)[((size_t)(b * T_ + row0) * CDIM + col) >> 1] =
            pack_h2(yacc[dt8][0] * il0, yacc[dt8][1] * il0);
        ((uint32_t*)g_yf)[((size_t)(b * T_ + row0 + 8) * CDIM + col) >> 1] =
            pack_h2(yacc[dt8][2] * il1, yacc[dt8][3] * il1);
    }
}

// ============================================================
// launch
// ============================================================
extern "C" void kernel_launch(void* const* d_in, const int* in_sizes, int n_in,
                              void* d_out, int out_size)
{
    const float* x   = (const float*)d_in[0];
    const float* Wq  = (const float*)d_in[1];
    const float* Wk  = (const float*)d_in[2];
    const float* Wv  = (const float*)d_in[3];
    const float* Wku = (const float*)d_in[4];
    const float* Wvu = (const float*)d_in[5];
    const float* Wc  = (const float*)d_in[6];

    float* out      = (float*)d_out;
    float* y_out    = out;
    float* klat_out = out + Y_ELEMS;
    float* vlat_out = out + Y_ELEMS + KL_ELEMS;

    __half *xf, *yf, *wf;
    cudaGetSymbolAddress((void**)&xf, g_xf);
    cudaGetSymbolAddress((void**)&yf, g_yf);
    cudaGetSymbolAddress((void**)&wf, g_wf);

    cudaFuncSetAttribute(attn_mma_kernel, cudaFuncAttributeMaxDynamicSharedMemorySize, AT_SMEM);
    cudaFuncSetAttribute(proj_gemm, cudaFuncAttributeMaxDynamicSharedMemorySize, GS_SMEM);
    cudaFuncSetAttribute(hgemm_wc, cudaFuncAttributeMaxDynamicSharedMemorySize, GS_SMEM);

    rope_table_kernel<<<T_, 64>>>();
    cvt_x_kernel<<<4096, 256>>>(x);
    cvt_w_kernel<<<3072, 256>>>(Wq, Wk, Wv, Wc);

    dim3 gp(8, (B_ * T_) / 128, 2);
    proj_gemm<<<gp, 256, GS_SMEM>>>(xf, wf, klat_out, vlat_out);

    upproj_rope_kernel<<<B_ * T_ / 4, 256>>>(klat_out, vlat_out, Wku, Wvu);

    dim3 ga(T_ / 128, H_, B_);
    attn_mma_kernel<<<ga, 256, AT_SMEM>>>();

    dim3 gc(8, (B_ * T_) / 128);
    hgemm_wc<<<gc, 256, GS_SMEM>>>(yf, wf + WC_OFF, y_out);
}